// round 12
// baseline (speedup 1.0000x reference)
#include <cuda_runtime.h>
#include <cuda_bf16.h>
#include <cuda_fp16.h>
typedef unsigned int u32; typedef unsigned long long u64;

#define NELEM (4*4096*64)
__device__ __nv_bfloat16 g_Khi[NELEM], g_Klo[NELEM];   // [b][n][c]
__device__ __nv_bfloat16 g_Qhi[NELEM], g_Qlo[NELEM];   // [b][m][c]
__device__ __half        g_Vh [NELEM];                  // [b][n][c]  fp16
__device__ float g_E[NELEM];                            // [b][c][n]

#define SWZ(row, chunk) (((u32)(row) << 7) + ((u32)(((chunk) ^ ((row) & 7))) << 4))

__device__ __forceinline__ u32 smem_u32(const void* p) {
    u32 a; asm("{ .reg .u64 t; cvta.to.shared.u64 t, %1; cvt.u32.u64 %0, t; }" : "=r"(a) : "l"(p)); return a;
}
__device__ __forceinline__ void cpa16(u32 dst, const void* src) {
    asm volatile("cp.async.cg.shared.global [%0], [%1], 16;" :: "r"(dst), "l"(src));
}
__device__ __forceinline__ void cpa_commit() { asm volatile("cp.async.commit_group;"); }
__device__ __forceinline__ void cpa_wait0()  { asm volatile("cp.async.wait_group 0;"); }
__device__ __forceinline__ void ldsm4(u32* r, u32 a) {
    asm volatile("ldmatrix.sync.aligned.m8n8.x4.shared.b16 {%0,%1,%2,%3},[%4];"
        : "=r"(r[0]), "=r"(r[1]), "=r"(r[2]), "=r"(r[3]) : "r"(a));
}
__device__ __forceinline__ void ldsm4t(u32* r, u32 a) {
    asm volatile("ldmatrix.sync.aligned.m8n8.x4.trans.shared.b16 {%0,%1,%2,%3},[%4];"
        : "=r"(r[0]), "=r"(r[1]), "=r"(r[2]), "=r"(r[3]) : "r"(a));
}
__device__ __forceinline__ void mma_bf16(float* d, const u32* a, u32 b0, u32 b1) {
    asm volatile("mma.sync.aligned.m16n8k16.row.col.f32.bf16.bf16.f32 "
        "{%0,%1,%2,%3},{%4,%5,%6,%7},{%8,%9},{%0,%1,%2,%3};"
        : "+f"(d[0]), "+f"(d[1]), "+f"(d[2]), "+f"(d[3])
        : "r"(a[0]), "r"(a[1]), "r"(a[2]), "r"(a[3]), "r"(b0), "r"(b1));
}
__device__ __forceinline__ void mma_f16(float* d, const u32* a, u32 b0, u32 b1) {
    asm volatile("mma.sync.aligned.m16n8k16.row.col.f32.f16.f16.f32 "
        "{%0,%1,%2,%3},{%4,%5,%6,%7},{%8,%9},{%0,%1,%2,%3};"
        : "+f"(d[0]), "+f"(d[1]), "+f"(d[2]), "+f"(d[3])
        : "r"(a[0]), "r"(a[1]), "r"(a[2]), "r"(a[3]), "r"(b0), "r"(b1));
}
__device__ __forceinline__ u32 pack_f16(float lo, float hi) {
    __half2 h = __floats2half2_rn(lo, hi);
    return *(u32*)&h;
}
__device__ __forceinline__ u64 pk2(float x, float y) {
    u64 r; asm("mov.b64 %0, {%1,%2};" : "=l"(r) : "f"(x), "f"(y)); return r;
}
__device__ __forceinline__ float2 upk2(u64 v) {
    float2 f; asm("mov.b64 {%0,%1}, %2;" : "=f"(f.x), "=f"(f.y) : "l"(v)); return f;
}
__device__ __forceinline__ void fma2(u64 &d, u64 a, u64 b) {
    asm("fma.rn.f32x2 %0, %1, %2, %0;" : "+l"(d) : "l"(a), "l"(b));
}

// ========== Kernel 1: projections (R11, unchanged) ================================
#define PJ_WT 8192
#define PJ_SMEM ((8192 + 128*68) * 4)

__global__ void __launch_bounds__(256) proj_kernel(
    const float* __restrict__ Hp, const float* __restrict__ Lp,
    const float* __restrict__ tw, const float* __restrict__ tb,
    const float* __restrict__ pw, const float* __restrict__ pb,
    const float* __restrict__ gw, const float* __restrict__ gb)
{
    extern __shared__ float sm[];
    float* sX = sm;
    const int proj = blockIdx.y, b = blockIdx.z, p0 = blockIdx.x << 6, tid = threadIdx.x;
    const float* W; const float* bias; int IC;
    if (proj == 0)      { W = tw; bias = tb; IC = 128; }
    else if (proj == 1) { W = pw; bias = pb; IC = 128; }
    else                { W = gw; bias = gb; IC = 64;  }

    for (int i = tid; i < IC * 64; i += 256) {
        int c = i >> 6, p = i & 63;
        const float* src = (proj == 2) ? Lp : ((c < 64) ? Hp : Lp);
        sX[i] = src[(((b << 6) + (c & 63)) << 12) + p0 + p];
    }
    for (int i = tid; i < 64 * IC; i += 256) {
        int oc = i / IC, c = i - oc * IC;
        sm[PJ_WT + c * 68 + oc] = W[i];
    }
    __syncthreads();

    const int to = tid >> 4, tp = tid & 15;
    u64 acc[4][2];
    #pragma unroll
    for (int i = 0; i < 4; i++) { acc[i][0] = 0ULL; acc[i][1] = 0ULL; }
    #pragma unroll 2
    for (int c = 0; c < IC; c++) {
        float4 w4 = *(const float4*)&sm[PJ_WT + c * 68 + 4 * to];
        u64 wv[4] = { pk2(w4.x, w4.x), pk2(w4.y, w4.y), pk2(w4.z, w4.z), pk2(w4.w, w4.w) };
        u64 x0 = *(const u64*)&sX[(c << 6) + 2 * tp];
        u64 x1 = *(const u64*)&sX[(c << 6) + 2 * tp + 32];
        #pragma unroll
        for (int i = 0; i < 4; i++) { fma2(acc[i][0], wv[i], x0); fma2(acc[i][1], wv[i], x1); }
    }
    __syncthreads();
    unsigned short* tHi = (unsigned short*)sm;                       // [64][72]
    unsigned short* tLo = (unsigned short*)((char*)sm + 9216);
    #pragma unroll
    for (int i = 0; i < 4; i++) {
        int o = 4 * to + i; float bo = bias[o];
        #pragma unroll
        for (int j = 0; j < 2; j++) {
            int px = 2 * tp + (j << 5);
            float2 a = upk2(acc[i][j]);
            float vx = a.x + bo, vy = a.y + bo;
            if (proj == 2) {
                tHi[px * 72 + o]       = __half_as_ushort(__float2half_rn(vx));
                tHi[(px + 1) * 72 + o] = __half_as_ushort(__float2half_rn(vy));
            } else {
                __nv_bfloat16 hx = __float2bfloat16_rn(vx), hy = __float2bfloat16_rn(vy);
                tHi[px * 72 + o]       = *(unsigned short*)&hx;
                tHi[(px + 1) * 72 + o] = *(unsigned short*)&hy;
                __nv_bfloat16 lx = __float2bfloat16_rn(vx - __bfloat162float(hx));
                __nv_bfloat16 ly = __float2bfloat16_rn(vy - __bfloat162float(hy));
                tLo[px * 72 + o]       = *(unsigned short*)&lx;
                tLo[(px + 1) * 72 + o] = *(unsigned short*)&ly;
            }
        }
    }
    __syncthreads();
    if (proj == 2) {
        uint4* dh = (uint4*)(g_Vh + ((size_t)b * 4096 + p0) * 64);
        for (int u = tid; u < 512; u += 256) {
            int row = u >> 3, cc = u & 7;
            dh[u] = *(const uint4*)&tHi[row * 72 + cc * 8];
        }
    } else {
        __nv_bfloat16* dHi = (proj == 0) ? g_Khi : g_Qhi;
        __nv_bfloat16* dLo = (proj == 0) ? g_Klo : g_Qlo;
        uint4* dh = (uint4*)(dHi + ((size_t)b * 4096 + p0) * 64);
        uint4* dl = (uint4*)(dLo + ((size_t)b * 4096 + p0) * 64);
        for (int u = tid; u < 512; u += 256) {
            int row = u >> 3, cc = u & 7;
            dh[u] = *(const uint4*)&tHi[row * 72 + cc * 8];
            dl[u] = *(const uint4*)&tLo[row * 72 + cc * 8];
        }
    }
}

// ======= Kernel 2: HMMA flash attention, 64-row Q tiles, 2 CTAs/SM ================
// smem: K0 32K | K1 32K | V0 16K | V1 16K | Qstage 8K | sums = 114944 B
#define A_K0 0
#define A_V0 65536
#define A_QS 98304
#define ATTN_SMEM 107520    // 96K buffers + 8K stage + pad/sums

__global__ void __launch_bounds__(256, 2) attn_kernel()
{
    extern __shared__ char smem[];
    const int tid = threadIdx.x, w = tid >> 5, l = tid & 31;
    const int qw = w & 3, kw = w >> 2;           // 4 q-groups (16 rows) x 2 key-halves
    const int b = blockIdx.y, m0 = blockIdx.x << 6;
    const u32 sb  = smem_u32(smem);
    const u32 sK0 = sb + A_K0;     // buf stride 32768 (kh +0, kl +16384)
    const u32 sV0 = sb + A_V0;     // buf stride 16384
    const u32 sQS = sb + A_QS;     // 8K transient Q staging

    const int R = qw << 4;
    u32 qh[4][4], ql[4][4];
    u32 qaddr[4];
    {
        int arow = R + (l & 15);
        #pragma unroll
        for (int kk = 0; kk < 4; kk++) qaddr[kk] = SWZ(arow, kk * 2 + (l >> 4));
    }
    // stage Qh (8K), also start K0/V0 loads
    for (int u = tid; u < 512; u += 256) {
        int row = u >> 3, ch = u & 7;
        cpa16(sQS + SWZ(row, ch), g_Qhi + ((size_t)(b * 4096 + m0 + row)) * 64 + ch * 8);
    }
    cpa_commit();
    for (int u = tid; u < 1024; u += 256) {
        int row = u >> 3, ch = u & 7;
        size_t gk = ((size_t)(b * 4096 + row)) * 64 + ch * 8;
        u32 d = SWZ(row, ch);
        cpa16(sK0 + d, g_Khi + gk);
        cpa16(sK0 + 16384 + d, g_Klo + gk);
        cpa16(sV0 + d, g_Vh + gk);
    }
    cpa_commit();
    asm volatile("cp.async.wait_group 1;");
    __syncthreads();
    #pragma unroll
    for (int kk = 0; kk < 4; kk++) ldsm4(qh[kk], sQS + qaddr[kk]);
    __syncthreads();
    // stage Ql into same region
    for (int u = tid; u < 512; u += 256) {
        int row = u >> 3, ch = u & 7;
        cpa16(sQS + SWZ(row, ch), g_Qlo + ((size_t)(b * 4096 + m0 + row)) * 64 + ch * 8);
    }
    cpa_commit(); cpa_wait0(); __syncthreads();
    #pragma unroll
    for (int kk = 0; kk < 4; kk++) ldsm4(ql[kk], sQS + qaddr[kk]);

    float esum[2] = {0.f, 0.f};
    float mx[2] = {-1e30f, -1e30f};
    float eacc[8][4];
    #pragma unroll
    for (int j = 0; j < 8; j++)
        #pragma unroll
        for (int q = 0; q < 4; q++) eacc[j][q] = 0.f;

    const int krow  = (kw << 6) + (l & 7) + ((l & 16) ? 8 : 0);
    const int kcsel = (l >> 3) & 1;
    const int vrow  = (kw << 6) + (l & 7) + ((l & 8) ? 8 : 0);
    const int vcsel = (l >> 4) & 1;

    for (int kt = 0; kt < 32; kt++) {
        const u32 kb = sK0 + (u32)(kt & 1) * 32768;
        const u32 vb = sV0 + (u32)(kt & 1) * 16384;

        if (kt + 1 < 32) {
            int n1 = (kt + 1) << 7;
            u32 kd = sK0 + (u32)((kt + 1) & 1) * 32768;
            u32 vd = sV0 + (u32)((kt + 1) & 1) * 16384;
            for (int u = tid; u < 1024; u += 256) {
                int row = u >> 3, ch = u & 7;
                size_t g = ((size_t)(b * 4096 + n1 + row)) * 64 + ch * 8;
                u32 d = SWZ(row, ch);
                cpa16(kd + d, g_Khi + g);
                cpa16(kd + 16384 + d, g_Klo + g);
                cpa16(vd + d, g_Vh + g);
            }
            cpa_commit();
        }

        #pragma unroll
        for (int sbk = 0; sbk < 2; sbk++) {
            float s[4][4];
            #pragma unroll
            for (int nt = 0; nt < 4; nt++)
                #pragma unroll
                for (int q = 0; q < 4; q++) s[nt][q] = 0.f;

            #pragma unroll
            for (int nt2 = 0; nt2 < 2; nt2++) {
                #pragma unroll
                for (int kk = 0; kk < 4; kk++) {
                    u32 kh[4], klo[4];
                    int rr = sbk * 32 + nt2 * 16 + krow;
                    int ch = kk * 2 + kcsel;
                    ldsm4(kh,  kb + SWZ(rr, ch));
                    ldsm4(klo, kb + 16384 + SWZ(rr, ch));
                    mma_bf16(s[nt2 * 2 + 0], qh[kk], kh[0], kh[1]);
                    mma_bf16(s[nt2 * 2 + 0], qh[kk], klo[0], klo[1]);
                    mma_bf16(s[nt2 * 2 + 0], ql[kk], kh[0], kh[1]);
                    mma_bf16(s[nt2 * 2 + 1], qh[kk], kh[2], kh[3]);
                    mma_bf16(s[nt2 * 2 + 1], qh[kk], klo[2], klo[3]);
                    mma_bf16(s[nt2 * 2 + 1], ql[kk], kh[2], kh[3]);
                }
            }

            // online softmax
            float t0 = s[0][0], t1 = s[0][2];
            #pragma unroll
            for (int nt = 0; nt < 4; nt++) {
                t0 = fmaxf(t0, fmaxf(s[nt][0], s[nt][1]));
                t1 = fmaxf(t1, fmaxf(s[nt][2], s[nt][3]));
            }
            t0 = fmaxf(t0, __shfl_xor_sync(0xffffffffu, t0, 1));
            t0 = fmaxf(t0, __shfl_xor_sync(0xffffffffu, t0, 2));
            t1 = fmaxf(t1, __shfl_xor_sync(0xffffffffu, t1, 1));
            t1 = fmaxf(t1, __shfl_xor_sync(0xffffffffu, t1, 2));
            float mn0 = fmaxf(mx[0], t0), mn1 = fmaxf(mx[1], t1);
            float a0 = __expf(mx[0] - mn0), a1 = __expf(mx[1] - mn1);
            mx[0] = mn0; mx[1] = mn1;
            esum[0] *= a0; esum[1] *= a1;
            #pragma unroll
            for (int j = 0; j < 8; j++) {
                eacc[j][0] *= a0; eacc[j][1] *= a0;
                eacc[j][2] *= a1; eacc[j][3] *= a1;
            }
            u32 ph[2][4];
            #pragma unroll
            for (int nt = 0; nt < 4; nt++) {
                float e0 = __expf(s[nt][0] - mn0);
                float e1 = __expf(s[nt][1] - mn0);
                float e2 = __expf(s[nt][2] - mn1);
                float e3 = __expf(s[nt][3] - mn1);
                esum[0] += e0 + e1; esum[1] += e2 + e3;
                ph[nt >> 1][((nt & 1) << 1) + 0] = pack_f16(e0, e1);
                ph[nt >> 1][((nt & 1) << 1) + 1] = pack_f16(e2, e3);
            }

            #pragma unroll
            for (int t = 0; t < 2; t++) {
                #pragma unroll
                for (int cb = 0; cb < 4; cb++) {
                    u32 vh[4];
                    int rr = sbk * 32 + t * 16 + vrow;
                    int ch = cb * 2 + vcsel;
                    ldsm4t(vh, vb + SWZ(rr, ch));
                    mma_f16(eacc[cb * 2 + 0], ph[t], vh[0], vh[1]);
                    mma_f16(eacc[cb * 2 + 1], ph[t], vh[2], vh[3]);
                }
            }
        }

        cpa_wait0();
        __syncthreads();
    }

    #pragma unroll
    for (int hh = 0; hh < 2; hh++) {
        #pragma unroll
        for (int off = 1; off < 4; off <<= 1)
            esum[hh] += __shfl_xor_sync(0xffffffffu, esum[hh], off);
    }

    // merge key-half partials (rows 0..63 of this tile)
    const int gr = l >> 2, c0 = 2 * (l & 3);
    const int r0 = R + gr, r1 = r0 + 8;
    float* sPart = (float*)smem;                     // [64][66] = 16896 B
    float* sSum  = (float*)(smem + 35840);           // [64]
    float* sMax  = (float*)(smem + 36096);           // [64]
    if (kw == 1) {
        #pragma unroll
        for (int j = 0; j < 8; j++) {
            sPart[r0 * 66 + j * 8 + c0]     = eacc[j][0];
            sPart[r0 * 66 + j * 8 + c0 + 1] = eacc[j][1];
            sPart[r1 * 66 + j * 8 + c0]     = eacc[j][2];
            sPart[r1 * 66 + j * 8 + c0 + 1] = eacc[j][3];
        }
        if ((l & 3) == 0) {
            sSum[r0] = esum[0]; sSum[r1] = esum[1];
            sMax[r0] = mx[0];   sMax[r1] = mx[1];
        }
    }
    __syncthreads();
    float* sE = (float*)(smem + 17408);              // [64][68] = 17408 B
    if (kw == 0) {
        float mb0 = sMax[r0], mb1 = sMax[r1];
        float M0 = fmaxf(mx[0], mb0), M1 = fmaxf(mx[1], mb1);
        float fa0 = __expf(mx[0] - M0), fb0 = __expf(mb0 - M0);
        float fa1 = __expf(mx[1] - M1), fb1 = __expf(mb1 - M1);
        float inv0 = 1.f / (esum[0] * fa0 + sSum[r0] * fb0);
        float inv1 = 1.f / (esum[1] * fa1 + sSum[r1] * fb1);
        #pragma unroll
        for (int j = 0; j < 8; j++) {
            int c = 8 * j + c0;
            sE[c * 68 + r0]       = (eacc[j][0] * fa0 + sPart[r0 * 66 + j * 8 + c0]     * fb0) * inv0;
            sE[(c + 1) * 68 + r0] = (eacc[j][1] * fa0 + sPart[r0 * 66 + j * 8 + c0 + 1] * fb0) * inv0;
            sE[c * 68 + r1]       = (eacc[j][2] * fa1 + sPart[r1 * 66 + j * 8 + c0]     * fb1) * inv1;
            sE[(c + 1) * 68 + r1] = (eacc[j][3] * fa1 + sPart[r1 * 66 + j * 8 + c0 + 1] * fb1) * inv1;
        }
    }
    __syncthreads();
    for (int u = tid; u < 1024; u += 256) {
        int c = u >> 4, q = u & 15;
        float4 v = *(float4*)&sE[c * 68 + q * 4];
        *(float4*)&g_E[(((b << 6) + c) << 12) + m0 + q * 4] = v;
    }
}

// ====== Kernel 3: conv3x3 + BN + ReLU + residual (256 thr, 4 rows/CTA) ============
__global__ void __launch_bounds__(256) conv_kernel(
    const float* __restrict__ Hp,
    const float* __restrict__ cw, const float* __restrict__ cb,
    const float* __restrict__ gamma, const float* __restrict__ beta,
    const float* __restrict__ mean, const float* __restrict__ var,
    float* __restrict__ out)
{
    extern __shared__ float sW[];  // [ic*9+kk][32]
    const int tid = threadIdx.x, b = blockIdx.y, y0 = blockIdx.x << 2;
    const int oh = blockIdx.z << 5;
    for (int i = tid; i < 64 * 9 * 32; i += 256) {
        int ocl = i / 576, rem = i - ocl * 576;
        sW[rem * 32 + ocl] = cw[(oh + ocl) * 576 + rem];
    }
    __syncthreads();
    const int y = y0 + (tid >> 6), x = tid & 63;
    u64 acc2[16];
    #pragma unroll
    for (int i = 0; i < 16; i++) acc2[i] = 0ULL;
    for (int ic = 0; ic < 64; ic++) {
        const float* src = &g_E[(((b << 6) + ic) << 12)];
        float in9[9];
        #pragma unroll
        for (int dy = 0; dy < 3; dy++) {
            int yy = y + dy - 1; bool yok = (yy >= 0) && (yy < 64);
            #pragma unroll
            for (int dx = 0; dx < 3; dx++) {
                int xx = x + dx - 1;
                in9[dy * 3 + dx] = (yok && xx >= 0 && xx < 64) ? src[(yy << 6) + xx] : 0.f;
            }
        }
        #pragma unroll
        for (int kk = 0; kk < 9; kk++) {
            u64 iv = pk2(in9[kk], in9[kk]);
            const u64* wr = (const u64*)&sW[(ic * 9 + kk) << 5];
            #pragma unroll
            for (int q = 0; q < 16; q++) fma2(acc2[q], iv, wr[q]);
        }
    }
    const int pix = (y << 6) + x;
    #pragma unroll
    for (int q = 0; q < 16; q++) {
        float2 a = upk2(acc2[q]);
        #pragma unroll
        for (int h = 0; h < 2; h++) {
            int oc = oh + 2 * q + h;
            float v = (h ? a.y : a.x) + cb[oc];
            v = (v - mean[oc]) * (gamma[oc] * rsqrtf(var[oc] + 1e-5f)) + beta[oc];
            v = fmaxf(v, 0.f);
            int idx = (((b << 6) + oc) << 12) + pix;
            out[idx] = Hp[idx] + v;
        }
    }
}

extern "C" void kernel_launch(void* const* d_in, const int* in_sizes, int n_in,
                              void* d_out, int out_size)
{
    const float* Hp = (const float*)d_in[0];
    const float* Lp = (const float*)d_in[1];
    const float* tw = (const float*)d_in[2];  const float* tb = (const float*)d_in[3];
    const float* pw = (const float*)d_in[4];  const float* pb = (const float*)d_in[5];
    const float* gw = (const float*)d_in[6];  const float* gb = (const float*)d_in[7];
    const float* cw = (const float*)d_in[8];  const float* cb = (const float*)d_in[9];
    const float* gamma = (const float*)d_in[10]; const float* beta = (const float*)d_in[11];
    const float* mean = (const float*)d_in[12];  const float* var = (const float*)d_in[13];
    float* out = (float*)d_out;

    const int smem_conv = 64 * 9 * 32 * 4;
    cudaFuncSetAttribute(proj_kernel, cudaFuncAttributeMaxDynamicSharedMemorySize, PJ_SMEM);
    cudaFuncSetAttribute(attn_kernel, cudaFuncAttributeMaxDynamicSharedMemorySize, ATTN_SMEM);
    cudaFuncSetAttribute(conv_kernel, cudaFuncAttributeMaxDynamicSharedMemorySize, smem_conv);

    proj_kernel<<<dim3(64, 3, 4), 256, PJ_SMEM>>>(Hp, Lp, tw, tb, pw, pb, gw, gb);
    attn_kernel<<<dim3(64, 4), 256, ATTN_SMEM>>>();
    conv_kernel<<<dim3(16, 4, 2), 256, smem_conv>>>(Hp, cw, cb, gamma, beta, mean, var, out);
}

// round 13
// speedup vs baseline: 1.0675x; 1.0675x over previous
#include <cuda_runtime.h>
#include <cuda_bf16.h>
#include <cuda_fp16.h>
typedef unsigned int u32; typedef unsigned long long u64;

#define NELEM (4*4096*64)
__device__ __nv_bfloat16 g_Khi[NELEM], g_Klo[NELEM];   // [b][n][c]
__device__ __nv_bfloat16 g_Qhi[NELEM], g_Qlo[NELEM];   // [b][m][c]
__device__ __half        g_Vh [NELEM];                  // [b][n][c]  fp16
__device__ float g_E[NELEM];                            // [b][c][n]

#define SWZ(row, chunk) (((u32)(row) << 7) + ((u32)(((chunk) ^ ((row) & 7))) << 4))

__device__ __forceinline__ u32 smem_u32(const void* p) {
    u32 a; asm("{ .reg .u64 t; cvta.to.shared.u64 t, %1; cvt.u32.u64 %0, t; }" : "=r"(a) : "l"(p)); return a;
}
__device__ __forceinline__ void cpa16(u32 dst, const void* src) {
    asm volatile("cp.async.cg.shared.global [%0], [%1], 16;" :: "r"(dst), "l"(src));
}
__device__ __forceinline__ void cpa_commit() { asm volatile("cp.async.commit_group;"); }
__device__ __forceinline__ void cpa_wait0()  { asm volatile("cp.async.wait_group 0;"); }
__device__ __forceinline__ void ldsm4(u32* r, u32 a) {
    asm volatile("ldmatrix.sync.aligned.m8n8.x4.shared.b16 {%0,%1,%2,%3},[%4];"
        : "=r"(r[0]), "=r"(r[1]), "=r"(r[2]), "=r"(r[3]) : "r"(a));
}
__device__ __forceinline__ void ldsm4t(u32* r, u32 a) {
    asm volatile("ldmatrix.sync.aligned.m8n8.x4.trans.shared.b16 {%0,%1,%2,%3},[%4];"
        : "=r"(r[0]), "=r"(r[1]), "=r"(r[2]), "=r"(r[3]) : "r"(a));
}
__device__ __forceinline__ void mma_bf16(float* d, const u32* a, u32 b0, u32 b1) {
    asm volatile("mma.sync.aligned.m16n8k16.row.col.f32.bf16.bf16.f32 "
        "{%0,%1,%2,%3},{%4,%5,%6,%7},{%8,%9},{%0,%1,%2,%3};"
        : "+f"(d[0]), "+f"(d[1]), "+f"(d[2]), "+f"(d[3])
        : "r"(a[0]), "r"(a[1]), "r"(a[2]), "r"(a[3]), "r"(b0), "r"(b1));
}
__device__ __forceinline__ void mma_f16(float* d, const u32* a, u32 b0, u32 b1) {
    asm volatile("mma.sync.aligned.m16n8k16.row.col.f32.f16.f16.f32 "
        "{%0,%1,%2,%3},{%4,%5,%6,%7},{%8,%9},{%0,%1,%2,%3};"
        : "+f"(d[0]), "+f"(d[1]), "+f"(d[2]), "+f"(d[3])
        : "r"(a[0]), "r"(a[1]), "r"(a[2]), "r"(a[3]), "r"(b0), "r"(b1));
}
__device__ __forceinline__ u32 pack_f16(float lo, float hi) {
    __half2 h = __floats2half2_rn(lo, hi);
    return *(u32*)&h;
}
__device__ __forceinline__ u64 pk2(float x, float y) {
    u64 r; asm("mov.b64 %0, {%1,%2};" : "=l"(r) : "f"(x), "f"(y)); return r;
}
__device__ __forceinline__ float2 upk2(u64 v) {
    float2 f; asm("mov.b64 {%0,%1}, %2;" : "=f"(f.x), "=f"(f.y) : "l"(v)); return f;
}
__device__ __forceinline__ void fma2(u64 &d, u64 a, u64 b) {
    asm("fma.rn.f32x2 %0, %1, %2, %0;" : "+l"(d) : "l"(a), "l"(b));
}

// ========== Kernel 1: projections (R11 + register unlock) =========================
#define PJ_WT 8192
#define PJ_SMEM ((8192 + 128*68) * 4)

__global__ void __launch_bounds__(256, 3) proj_kernel(
    const float* __restrict__ Hp, const float* __restrict__ Lp,
    const float* __restrict__ tw, const float* __restrict__ tb,
    const float* __restrict__ pw, const float* __restrict__ pb,
    const float* __restrict__ gw, const float* __restrict__ gb)
{
    extern __shared__ float sm[];
    float* sX = sm;
    const int proj = blockIdx.y, b = blockIdx.z, p0 = blockIdx.x << 6, tid = threadIdx.x;
    const float* W; const float* bias; int IC;
    if (proj == 0)      { W = tw; bias = tb; IC = 128; }
    else if (proj == 1) { W = pw; bias = pb; IC = 128; }
    else                { W = gw; bias = gb; IC = 64;  }

    for (int i = tid; i < IC * 64; i += 256) {
        int c = i >> 6, p = i & 63;
        const float* src = (proj == 2) ? Lp : ((c < 64) ? Hp : Lp);
        sX[i] = src[(((b << 6) + (c & 63)) << 12) + p0 + p];
    }
    for (int i = tid; i < 64 * IC; i += 256) {
        int oc = i / IC, c = i - oc * IC;
        sm[PJ_WT + c * 68 + oc] = W[i];
    }
    __syncthreads();

    const int to = tid >> 4, tp = tid & 15;
    u64 acc[4][2];
    #pragma unroll
    for (int i = 0; i < 4; i++) { acc[i][0] = 0ULL; acc[i][1] = 0ULL; }
    #pragma unroll 4
    for (int c = 0; c < IC; c++) {
        float4 w4 = *(const float4*)&sm[PJ_WT + c * 68 + 4 * to];
        u64 wv[4] = { pk2(w4.x, w4.x), pk2(w4.y, w4.y), pk2(w4.z, w4.z), pk2(w4.w, w4.w) };
        u64 x0 = *(const u64*)&sX[(c << 6) + 2 * tp];
        u64 x1 = *(const u64*)&sX[(c << 6) + 2 * tp + 32];
        #pragma unroll
        for (int i = 0; i < 4; i++) { fma2(acc[i][0], wv[i], x0); fma2(acc[i][1], wv[i], x1); }
    }
    __syncthreads();
    unsigned short* tHi = (unsigned short*)sm;                       // [64][72]
    unsigned short* tLo = (unsigned short*)((char*)sm + 9216);
    #pragma unroll
    for (int i = 0; i < 4; i++) {
        int o = 4 * to + i; float bo = bias[o];
        #pragma unroll
        for (int j = 0; j < 2; j++) {
            int px = 2 * tp + (j << 5);
            float2 a = upk2(acc[i][j]);
            float vx = a.x + bo, vy = a.y + bo;
            if (proj == 2) {
                tHi[px * 72 + o]       = __half_as_ushort(__float2half_rn(vx));
                tHi[(px + 1) * 72 + o] = __half_as_ushort(__float2half_rn(vy));
            } else {
                __nv_bfloat16 hx = __float2bfloat16_rn(vx), hy = __float2bfloat16_rn(vy);
                tHi[px * 72 + o]       = *(unsigned short*)&hx;
                tHi[(px + 1) * 72 + o] = *(unsigned short*)&hy;
                __nv_bfloat16 lx = __float2bfloat16_rn(vx - __bfloat162float(hx));
                __nv_bfloat16 ly = __float2bfloat16_rn(vy - __bfloat162float(hy));
                tLo[px * 72 + o]       = *(unsigned short*)&lx;
                tLo[(px + 1) * 72 + o] = *(unsigned short*)&ly;
            }
        }
    }
    __syncthreads();
    if (proj == 2) {
        uint4* dh = (uint4*)(g_Vh + ((size_t)b * 4096 + p0) * 64);
        for (int u = tid; u < 512; u += 256) {
            int row = u >> 3, cc = u & 7;
            dh[u] = *(const uint4*)&tHi[row * 72 + cc * 8];
        }
    } else {
        __nv_bfloat16* dHi = (proj == 0) ? g_Khi : g_Qhi;
        __nv_bfloat16* dLo = (proj == 0) ? g_Klo : g_Qlo;
        uint4* dh = (uint4*)(dHi + ((size_t)b * 4096 + p0) * 64);
        uint4* dl = (uint4*)(dLo + ((size_t)b * 4096 + p0) * 64);
        for (int u = tid; u < 512; u += 256) {
            int row = u >> 3, cc = u & 7;
            dh[u] = *(const uint4*)&tHi[row * 72 + cc * 8];
            dl[u] = *(const uint4*)&tLo[row * 72 + cc * 8];
        }
    }
}

// ================= Kernel 2: HMMA flash attention (R8/R11 proven) =================
#define ATTN_SMEM 132096

__global__ void __launch_bounds__(256, 1) attn_kernel()
{
    extern __shared__ char smem[];
    const int tid = threadIdx.x, w = tid >> 5, l = tid & 31;
    const int qw = w & 3, kw = w >> 2;
    const int b = blockIdx.y, m0 = blockIdx.x << 7;
    const u32 sb  = smem_u32(smem);
    const u32 sQh = sb, sQl = sb + 16384;
    const u32 sK0 = sb + 32768;
    const u32 sV0 = sb + 98304;

    for (int u = tid; u < 1024; u += 256) {
        int row = u >> 3, ch = u & 7;
        size_t gq = ((size_t)(b * 4096 + m0 + row)) * 64 + ch * 8;
        size_t gk = ((size_t)(b * 4096 + row)) * 64 + ch * 8;
        u32 d = SWZ(row, ch);
        cpa16(sQh + d, g_Qhi + gq);
        cpa16(sQl + d, g_Qlo + gq);
        cpa16(sK0 + d, g_Khi + gk);
        cpa16(sK0 + 16384 + d, g_Klo + gk);
        cpa16(sV0 + d, g_Vh + gk);
    }
    cpa_commit(); cpa_wait0(); __syncthreads();

    const int R = qw << 5;
    u32 qh[8][4], ql[8][4];
    #pragma unroll
    for (int m = 0; m < 2; m++) {
        int arow = R + m * 16 + (l & 15);
        #pragma unroll
        for (int kk = 0; kk < 4; kk++) {
            u32 a = SWZ(arow, kk * 2 + (l >> 4));
            ldsm4(qh[m * 4 + kk], sQh + a);
            ldsm4(ql[m * 4 + kk], sQl + a);
        }
    }

    float esum[2][2] = {{0.f, 0.f}, {0.f, 0.f}};
    float mx[2][2] = {{-1e30f, -1e30f}, {-1e30f, -1e30f}};
    float eacc[2][8][4];
    #pragma unroll
    for (int m = 0; m < 2; m++)
        #pragma unroll
        for (int j = 0; j < 8; j++)
            #pragma unroll
            for (int q = 0; q < 4; q++) eacc[m][j][q] = 0.f;

    const int krow  = (kw << 6) + (l & 7) + ((l & 16) ? 8 : 0);
    const int kcsel = (l >> 3) & 1;
    const int vrow  = (kw << 6) + (l & 7) + ((l & 8) ? 8 : 0);
    const int vcsel = (l >> 4) & 1;

    for (int kt = 0; kt < 32; kt++) {
        const u32 kb = sK0 + (u32)(kt & 1) * 32768;
        const u32 vb = sV0 + (u32)(kt & 1) * 16384;

        if (kt + 1 < 32) {
            int n1 = (kt + 1) << 7;
            u32 kd = sK0 + (u32)((kt + 1) & 1) * 32768;
            u32 vd = sV0 + (u32)((kt + 1) & 1) * 16384;
            for (int u = tid; u < 1024; u += 256) {
                int row = u >> 3, ch = u & 7;
                size_t g = ((size_t)(b * 4096 + n1 + row)) * 64 + ch * 8;
                u32 d = SWZ(row, ch);
                cpa16(kd + d, g_Khi + g);
                cpa16(kd + 16384 + d, g_Klo + g);
                cpa16(vd + d, g_Vh + g);
            }
            cpa_commit();
        }

        #pragma unroll
        for (int sbk = 0; sbk < 2; sbk++) {
            float s[2][4][4];
            #pragma unroll
            for (int m = 0; m < 2; m++)
                #pragma unroll
                for (int nt = 0; nt < 4; nt++)
                    #pragma unroll
                    for (int q = 0; q < 4; q++) s[m][nt][q] = 0.f;

            #pragma unroll
            for (int nt2 = 0; nt2 < 2; nt2++) {
                #pragma unroll
                for (int kk = 0; kk < 4; kk++) {
                    u32 kh[4], klo[4];
                    int rr = sbk * 32 + nt2 * 16 + krow;
                    int ch = kk * 2 + kcsel;
                    ldsm4(kh,  kb + SWZ(rr, ch));
                    ldsm4(klo, kb + 16384 + SWZ(rr, ch));
                    #pragma unroll
                    for (int m = 0; m < 2; m++) {
                        mma_bf16(s[m][nt2 * 2 + 0], qh[m * 4 + kk], kh[0], kh[1]);
                        mma_bf16(s[m][nt2 * 2 + 0], qh[m * 4 + kk], klo[0], klo[1]);
                        mma_bf16(s[m][nt2 * 2 + 0], ql[m * 4 + kk], kh[0], kh[1]);
                        mma_bf16(s[m][nt2 * 2 + 1], qh[m * 4 + kk], kh[2], kh[3]);
                        mma_bf16(s[m][nt2 * 2 + 1], qh[m * 4 + kk], klo[2], klo[3]);
                        mma_bf16(s[m][nt2 * 2 + 1], ql[m * 4 + kk], kh[2], kh[3]);
                    }
                }
            }

            u32 ph[2][2][4];
            #pragma unroll
            for (int m = 0; m < 2; m++) {
                float t0 = s[m][0][0], t1 = s[m][0][2];
                #pragma unroll
                for (int nt = 0; nt < 4; nt++) {
                    t0 = fmaxf(t0, fmaxf(s[m][nt][0], s[m][nt][1]));
                    t1 = fmaxf(t1, fmaxf(s[m][nt][2], s[m][nt][3]));
                }
                t0 = fmaxf(t0, __shfl_xor_sync(0xffffffffu, t0, 1));
                t0 = fmaxf(t0, __shfl_xor_sync(0xffffffffu, t0, 2));
                t1 = fmaxf(t1, __shfl_xor_sync(0xffffffffu, t1, 1));
                t1 = fmaxf(t1, __shfl_xor_sync(0xffffffffu, t1, 2));
                float mn0 = fmaxf(mx[m][0], t0), mn1 = fmaxf(mx[m][1], t1);
                float a0 = __expf(mx[m][0] - mn0), a1 = __expf(mx[m][1] - mn1);
                mx[m][0] = mn0; mx[m][1] = mn1;
                esum[m][0] *= a0; esum[m][1] *= a1;
                #pragma unroll
                for (int j = 0; j < 8; j++) {
                    eacc[m][j][0] *= a0; eacc[m][j][1] *= a0;
                    eacc[m][j][2] *= a1; eacc[m][j][3] *= a1;
                }
                #pragma unroll
                for (int nt = 0; nt < 4; nt++) {
                    float e0 = __expf(s[m][nt][0] - mn0);
                    float e1 = __expf(s[m][nt][1] - mn0);
                    float e2 = __expf(s[m][nt][2] - mn1);
                    float e3 = __expf(s[m][nt][3] - mn1);
                    esum[m][0] += e0 + e1; esum[m][1] += e2 + e3;
                    ph[m][nt >> 1][((nt & 1) << 1) + 0] = pack_f16(e0, e1);
                    ph[m][nt >> 1][((nt & 1) << 1) + 1] = pack_f16(e2, e3);
                }
            }

            #pragma unroll
            for (int t = 0; t < 2; t++) {
                #pragma unroll
                for (int cb = 0; cb < 4; cb++) {
                    u32 vh[4];
                    int rr = sbk * 32 + t * 16 + vrow;
                    int ch = cb * 2 + vcsel;
                    ldsm4t(vh, vb + SWZ(rr, ch));
                    #pragma unroll
                    for (int m = 0; m < 2; m++) {
                        mma_f16(eacc[m][cb * 2 + 0], ph[m][t], vh[0], vh[1]);
                        mma_f16(eacc[m][cb * 2 + 1], ph[m][t], vh[2], vh[3]);
                    }
                }
            }
        }

        cpa_wait0();
        __syncthreads();
    }

    #pragma unroll
    for (int m = 0; m < 2; m++)
        #pragma unroll
        for (int hh = 0; hh < 2; hh++) {
            #pragma unroll
            for (int off = 1; off < 4; off <<= 1)
                esum[m][hh] += __shfl_xor_sync(0xffffffffu, esum[m][hh], off);
        }

    const int gr = l >> 2, c0 = 2 * (l & 3);
    float* sPart = (float*)smem;
    float* sSum  = (float*)(smem + 131072);
    float* sMax  = (float*)(smem + 131584);
    if (kw == 1) {
        #pragma unroll
        for (int m = 0; m < 2; m++) {
            int r0 = R + m * 16 + gr, r1 = r0 + 8;
            #pragma unroll
            for (int j = 0; j < 8; j++) {
                float* p  = &sPart[r0 * 66 + j * 8 + c0];
                float* p2 = &sPart[r1 * 66 + j * 8 + c0];
                p[0]  = eacc[m][j][0]; p[1]  = eacc[m][j][1];
                p2[0] = eacc[m][j][2]; p2[1] = eacc[m][j][3];
            }
            if ((l & 3) == 0) {
                sSum[r0] = esum[m][0]; sSum[r1] = esum[m][1];
                sMax[r0] = mx[m][0];   sMax[r1] = mx[m][1];
            }
        }
    }
    __syncthreads();
    float* sE = (float*)(smem + 65536);
    if (kw == 0) {
        #pragma unroll
        for (int m = 0; m < 2; m++) {
            int r0 = R + m * 16 + gr, r1 = r0 + 8;
            float mb0 = sMax[r0], mb1 = sMax[r1];
            float M0 = fmaxf(mx[m][0], mb0), M1 = fmaxf(mx[m][1], mb1);
            float fa0 = __expf(mx[m][0] - M0), fb0 = __expf(mb0 - M0);
            float fa1 = __expf(mx[m][1] - M1), fb1 = __expf(mb1 - M1);
            float inv0 = 1.f / (esum[m][0] * fa0 + sSum[r0] * fb0);
            float inv1 = 1.f / (esum[m][1] * fa1 + sSum[r1] * fb1);
            #pragma unroll
            for (int j = 0; j < 8; j++) {
                float* p  = &sPart[r0 * 66 + j * 8 + c0];
                float* p2 = &sPart[r1 * 66 + j * 8 + c0];
                int c = 8 * j + c0;
                sE[c * 132 + r0]       = (eacc[m][j][0] * fa0 + p[0]  * fb0) * inv0;
                sE[(c + 1) * 132 + r0] = (eacc[m][j][1] * fa0 + p[1]  * fb0) * inv0;
                sE[c * 132 + r1]       = (eacc[m][j][2] * fa1 + p2[0] * fb1) * inv1;
                sE[(c + 1) * 132 + r1] = (eacc[m][j][3] * fa1 + p2[1] * fb1) * inv1;
            }
        }
    }
    __syncthreads();
    for (int u = tid; u < 2048; u += 256) {
        int c = u >> 5, q = u & 31;
        float4 v = *(float4*)&sE[c * 132 + q * 4];
        *(float4*)&g_E[(((b << 6) + c) << 12) + m0 + q * 4] = v;
    }
}

// ============ Kernel 3: conv3x3 + BN + ReLU + residual (R8/R11 proven) =============
__global__ void __launch_bounds__(128) conv_kernel(
    const float* __restrict__ Hp,
    const float* __restrict__ cw, const float* __restrict__ cb,
    const float* __restrict__ gamma, const float* __restrict__ beta,
    const float* __restrict__ mean, const float* __restrict__ var,
    float* __restrict__ out)
{
    extern __shared__ float sW[];  // [ic*9+kk][32]
    const int tid = threadIdx.x, b = blockIdx.y, y0 = blockIdx.x << 1;
    const int oh = blockIdx.z << 5;
    for (int i = tid; i < 64 * 9 * 32; i += 128) {
        int ocl = i / 576, rem = i - ocl * 576;
        sW[rem * 32 + ocl] = cw[(oh + ocl) * 576 + rem];
    }
    __syncthreads();
    const int y = y0 + (tid >> 6), x = tid & 63;
    u64 acc2[16];
    #pragma unroll
    for (int i = 0; i < 16; i++) acc2[i] = 0ULL;
    for (int ic = 0; ic < 64; ic++) {
        const float* src = &g_E[(((b << 6) + ic) << 12)];
        float in9[9];
        #pragma unroll
        for (int dy = 0; dy < 3; dy++) {
            int yy = y + dy - 1; bool yok = (yy >= 0) && (yy < 64);
            #pragma unroll
            for (int dx = 0; dx < 3; dx++) {
                int xx = x + dx - 1;
                in9[dy * 3 + dx] = (yok && xx >= 0 && xx < 64) ? src[(yy << 6) + xx] : 0.f;
            }
        }
        #pragma unroll
        for (int kk = 0; kk < 9; kk++) {
            u64 iv = pk2(in9[kk], in9[kk]);
            const u64* wr = (const u64*)&sW[(ic * 9 + kk) << 5];
            #pragma unroll
            for (int q = 0; q < 16; q++) fma2(acc2[q], iv, wr[q]);
        }
    }
    const int pix = (y << 6) + x;
    #pragma unroll
    for (int q = 0; q < 16; q++) {
        float2 a = upk2(acc2[q]);
        #pragma unroll
        for (int h = 0; h < 2; h++) {
            int oc = oh + 2 * q + h;
            float v = (h ? a.y : a.x) + cb[oc];
            v = (v - mean[oc]) * (gamma[oc] * rsqrtf(var[oc] + 1e-5f)) + beta[oc];
            v = fmaxf(v, 0.f);
            int idx = (((b << 6) + oc) << 12) + pix;
            out[idx] = Hp[idx] + v;
        }
    }
}

extern "C" void kernel_launch(void* const* d_in, const int* in_sizes, int n_in,
                              void* d_out, int out_size)
{
    const float* Hp = (const float*)d_in[0];
    const float* Lp = (const float*)d_in[1];
    const float* tw = (const float*)d_in[2];  const float* tb = (const float*)d_in[3];
    const float* pw = (const float*)d_in[4];  const float* pb = (const float*)d_in[5];
    const float* gw = (const float*)d_in[6];  const float* gb = (const float*)d_in[7];
    const float* cw = (const float*)d_in[8];  const float* cb = (const float*)d_in[9];
    const float* gamma = (const float*)d_in[10]; const float* beta = (const float*)d_in[11];
    const float* mean = (const float*)d_in[12];  const float* var = (const float*)d_in[13];
    float* out = (float*)d_out;

    const int smem_conv = 64 * 9 * 32 * 4;
    cudaFuncSetAttribute(proj_kernel, cudaFuncAttributeMaxDynamicSharedMemorySize, PJ_SMEM);
    cudaFuncSetAttribute(attn_kernel, cudaFuncAttributeMaxDynamicSharedMemorySize, ATTN_SMEM);
    cudaFuncSetAttribute(conv_kernel, cudaFuncAttributeMaxDynamicSharedMemorySize, smem_conv);

    proj_kernel<<<dim3(64, 3, 4), 256, PJ_SMEM>>>(Hp, Lp, tw, tb, pw, pb, gw, gb);
    attn_kernel<<<dim3(32, 4), 256, ATTN_SMEM>>>();
    conv_kernel<<<dim3(32, 4, 2), 128, smem_conv>>>(Hp, cw, cb, gamma, beta, mean, var, out);
}

// round 14
// speedup vs baseline: 1.1336x; 1.0619x over previous
#include <cuda_runtime.h>
#include <cuda_bf16.h>
#include <cuda_fp16.h>
typedef unsigned int u32; typedef unsigned long long u64;

#define NELEM (4*4096*64)
__device__ __nv_bfloat16 g_Khi[NELEM], g_Klo[NELEM];   // [b][n][c]
__device__ __nv_bfloat16 g_Qhi[NELEM], g_Qlo[NELEM];   // [b][m][c]
__device__ __half        g_Vh [NELEM];                  // [b][n][c]  fp16
__device__ float g_E[NELEM];                            // [b][c][n]

#define SWZ(row, chunk) (((u32)(row) << 7) + ((u32)(((chunk) ^ ((row) & 7))) << 4))

__device__ __forceinline__ u32 smem_u32(const void* p) {
    u32 a; asm("{ .reg .u64 t; cvta.to.shared.u64 t, %1; cvt.u32.u64 %0, t; }" : "=r"(a) : "l"(p)); return a;
}
__device__ __forceinline__ void cpa16(u32 dst, const void* src) {
    asm volatile("cp.async.cg.shared.global [%0], [%1], 16;" :: "r"(dst), "l"(src));
}
__device__ __forceinline__ void cpa_commit() { asm volatile("cp.async.commit_group;"); }
__device__ __forceinline__ void cpa_wait0()  { asm volatile("cp.async.wait_group 0;"); }
__device__ __forceinline__ void ldsm4(u32* r, u32 a) {
    asm volatile("ldmatrix.sync.aligned.m8n8.x4.shared.b16 {%0,%1,%2,%3},[%4];"
        : "=r"(r[0]), "=r"(r[1]), "=r"(r[2]), "=r"(r[3]) : "r"(a));
}
__device__ __forceinline__ void ldsm4t(u32* r, u32 a) {
    asm volatile("ldmatrix.sync.aligned.m8n8.x4.trans.shared.b16 {%0,%1,%2,%3},[%4];"
        : "=r"(r[0]), "=r"(r[1]), "=r"(r[2]), "=r"(r[3]) : "r"(a));
}
__device__ __forceinline__ void mma_bf16(float* d, const u32* a, u32 b0, u32 b1) {
    asm volatile("mma.sync.aligned.m16n8k16.row.col.f32.bf16.bf16.f32 "
        "{%0,%1,%2,%3},{%4,%5,%6,%7},{%8,%9},{%0,%1,%2,%3};"
        : "+f"(d[0]), "+f"(d[1]), "+f"(d[2]), "+f"(d[3])
        : "r"(a[0]), "r"(a[1]), "r"(a[2]), "r"(a[3]), "r"(b0), "r"(b1));
}
__device__ __forceinline__ void mma_f16(float* d, const u32* a, u32 b0, u32 b1) {
    asm volatile("mma.sync.aligned.m16n8k16.row.col.f32.f16.f16.f32 "
        "{%0,%1,%2,%3},{%4,%5,%6,%7},{%8,%9},{%0,%1,%2,%3};"
        : "+f"(d[0]), "+f"(d[1]), "+f"(d[2]), "+f"(d[3])
        : "r"(a[0]), "r"(a[1]), "r"(a[2]), "r"(a[3]), "r"(b0), "r"(b1));
}
__device__ __forceinline__ u32 pack_f16(float lo, float hi) {
    __half2 h = __floats2half2_rn(lo, hi);
    return *(u32*)&h;
}
__device__ __forceinline__ u32 pack_bf16(float lo, float hi) {
    u32 r; asm("cvt.rn.bf16x2.f32 %0, %1, %2;" : "=r"(r) : "f"(hi), "f"(lo)); return r;
}
__device__ __forceinline__ u64 pk2(float x, float y) {
    u64 r; asm("mov.b64 %0, {%1,%2};" : "=l"(r) : "f"(x), "f"(y)); return r;
}
__device__ __forceinline__ float2 upk2(u64 v) {
    float2 f; asm("mov.b64 {%0,%1}, %2;" : "=f"(f.x), "=f"(f.y) : "l"(v)); return f;
}
__device__ __forceinline__ void fma2(u64 &d, u64 a, u64 b) {
    asm("fma.rn.f32x2 %0, %1, %2, %0;" : "+l"(d) : "l"(a), "l"(b));
}

// ========== Kernel 1: HMMA projections (split-bf16 3-product) ======================
// smem: Xhi [128][64]bf16 0..16K | Xlo 16K..32K | Whi 32K..40K(half0),40K..48K(half1)
//       Wlo 48K..64K   | epilogue tHi/tLo reuse 0..18.4K
#define PJ_SMEM 65536

__global__ void __launch_bounds__(256, 3) proj_kernel(
    const float* __restrict__ Hp, const float* __restrict__ Lp,
    const float* __restrict__ tw, const float* __restrict__ tb,
    const float* __restrict__ pw, const float* __restrict__ pb,
    const float* __restrict__ gw, const float* __restrict__ gb)
{
    extern __shared__ char smc[];
    const u32 sb = smem_u32(smc);
    const int proj = blockIdx.y, b = blockIdx.z, p0 = blockIdx.x << 6, tid = threadIdx.x;
    const int w = tid >> 5, l = tid & 31;
    const float* W; const float* bias; int IC;
    if (proj == 0)      { W = tw; bias = tb; IC = 128; }
    else if (proj == 1) { W = pw; bias = pb; IC = 128; }
    else                { W = gw; bias = gb; IC = 64;  }

    // stage X [c][64 px] as split bf16 (coalesced fp32 reads)
    for (int u = tid; u < IC * 32; u += 256) {
        int c = u >> 5, pp = (u & 31) << 1;
        const float* src = (proj == 2) ? Lp : ((c < 64) ? Hp : Lp);
        const float* s2 = &src[(((b << 6) + (c & 63)) << 12) + p0 + pp];
        float v0 = s2[0], v1 = s2[1];
        u32 hh = pack_bf16(v0, v1);
        float h0 = __uint_as_float(hh << 16), h1 = __uint_as_float(hh & 0xffff0000u);
        u32 ll = pack_bf16(v0 - h0, v1 - h1);
        u32 off = SWZ(c, pp >> 3) + ((pp & 7) << 1);
        *(u32*)(smc + off) = hh;
        *(u32*)(smc + 16384 + off) = ll;
    }
    // stage W [64 oc][IC c] as split bf16, two 64-c halves
    for (int u = tid; u < 64 * (IC >> 1); u += 256) {
        int oc = u / (IC >> 1), cp = (u % (IC >> 1)) << 1;
        float w0 = W[oc * IC + cp], w1 = W[oc * IC + cp + 1];
        u32 hh = pack_bf16(w0, w1);
        float h0 = __uint_as_float(hh << 16), h1 = __uint_as_float(hh & 0xffff0000u);
        u32 ll = pack_bf16(w0 - h0, w1 - h1);
        int half = cp >> 6, cl = cp & 63;
        u32 off = ((u32)half << 13) + SWZ(oc, cl >> 3) + ((cl & 7) << 1);
        *(u32*)(smc + 32768 + off) = hh;
        *(u32*)(smc + 49152 + off) = ll;
    }
    __syncthreads();

    // warp: mt = oc tile (16 rows), pxh = px half (32 cols)
    const int mt = w & 3, pxh = w >> 2;
    const int arow = mt * 16 + (l & 15);
    const int acs = l >> 4;
    const int brr = (l & 7) + ((l & 8) ? 8 : 0);
    const int bcs = (l >> 4) & 1;

    float acc[4][4];
    #pragma unroll
    for (int j = 0; j < 4; j++)
        #pragma unroll
        for (int q = 0; q < 4; q++) acc[j][q] = 0.f;

    const int K16 = IC >> 4;
    #pragma unroll 4
    for (int kk = 0; kk < K16; kk++) {
        u32 wh[4], wl[4];
        u32 aoff = ((u32)(kk >> 2) << 13) + SWZ(arow, ((kk & 3) << 1) + acs);
        ldsm4(wh, sb + 32768 + aoff);
        ldsm4(wl, sb + 49152 + aoff);
        int rr = (kk << 4) + brr;
        #pragma unroll
        for (int nb = 0; nb < 2; nb++) {
            u32 xh[4], xl[4];
            u32 boff = SWZ(rr, (pxh << 2) + (nb << 1) + bcs);
            ldsm4t(xh, sb + boff);
            ldsm4t(xl, sb + 16384 + boff);
            mma_bf16(acc[nb * 2 + 0], wh, xh[0], xh[1]);
            mma_bf16(acc[nb * 2 + 0], wh, xl[0], xl[1]);
            mma_bf16(acc[nb * 2 + 0], wl, xh[0], xh[1]);
            mma_bf16(acc[nb * 2 + 1], wh, xh[2], xh[3]);
            mma_bf16(acc[nb * 2 + 1], wh, xl[2], xl[3]);
            mma_bf16(acc[nb * 2 + 1], wl, xh[2], xh[3]);
        }
    }
    __syncthreads();

    // epilogue: fragments (oc rows r0/r1, px cols) -> [px][72] staging -> global
    unsigned short* tHi = (unsigned short*)smc;
    unsigned short* tLo = (unsigned short*)(smc + 9216);
    const int r0 = mt * 16 + (l >> 2), r1 = r0 + 8;
    const float b0v = bias[r0], b1v = bias[r1];
    #pragma unroll
    for (int j = 0; j < 4; j++) {
        int px = pxh * 32 + j * 8 + ((l & 3) << 1);
        float v00 = acc[j][0] + b0v, v01 = acc[j][1] + b0v;
        float v10 = acc[j][2] + b1v, v11 = acc[j][3] + b1v;
        if (proj == 2) {
            tHi[px * 72 + r0]       = __half_as_ushort(__float2half_rn(v00));
            tHi[(px + 1) * 72 + r0] = __half_as_ushort(__float2half_rn(v01));
            tHi[px * 72 + r1]       = __half_as_ushort(__float2half_rn(v10));
            tHi[(px + 1) * 72 + r1] = __half_as_ushort(__float2half_rn(v11));
        } else {
            __nv_bfloat16 h00 = __float2bfloat16_rn(v00), h01 = __float2bfloat16_rn(v01);
            __nv_bfloat16 h10 = __float2bfloat16_rn(v10), h11 = __float2bfloat16_rn(v11);
            tHi[px * 72 + r0]       = *(unsigned short*)&h00;
            tHi[(px + 1) * 72 + r0] = *(unsigned short*)&h01;
            tHi[px * 72 + r1]       = *(unsigned short*)&h10;
            tHi[(px + 1) * 72 + r1] = *(unsigned short*)&h11;
            __nv_bfloat16 l00 = __float2bfloat16_rn(v00 - __bfloat162float(h00));
            __nv_bfloat16 l01 = __float2bfloat16_rn(v01 - __bfloat162float(h01));
            __nv_bfloat16 l10 = __float2bfloat16_rn(v10 - __bfloat162float(h10));
            __nv_bfloat16 l11 = __float2bfloat16_rn(v11 - __bfloat162float(h11));
            tLo[px * 72 + r0]       = *(unsigned short*)&l00;
            tLo[(px + 1) * 72 + r0] = *(unsigned short*)&l01;
            tLo[px * 72 + r1]       = *(unsigned short*)&l10;
            tLo[(px + 1) * 72 + r1] = *(unsigned short*)&l11;
        }
    }
    __syncthreads();
    if (proj == 2) {
        uint4* dh = (uint4*)(g_Vh + ((size_t)b * 4096 + p0) * 64);
        for (int u = tid; u < 512; u += 256) {
            int row = u >> 3, cc = u & 7;
            dh[u] = *(const uint4*)&tHi[row * 72 + cc * 8];
        }
    } else {
        __nv_bfloat16* dHi = (proj == 0) ? g_Khi : g_Qhi;
        __nv_bfloat16* dLo = (proj == 0) ? g_Klo : g_Qlo;
        uint4* dh = (uint4*)(dHi + ((size_t)b * 4096 + p0) * 64);
        uint4* dl = (uint4*)(dLo + ((size_t)b * 4096 + p0) * 64);
        for (int u = tid; u < 512; u += 256) {
            int row = u >> 3, cc = u & 7;
            dh[u] = *(const uint4*)&tHi[row * 72 + cc * 8];
            dl[u] = *(const uint4*)&tLo[row * 72 + cc * 8];
        }
    }
}

// ================= Kernel 2: HMMA flash attention (R13, unchanged) =================
#define ATTN_SMEM 132096

__global__ void __launch_bounds__(256, 1) attn_kernel()
{
    extern __shared__ char smem[];
    const int tid = threadIdx.x, w = tid >> 5, l = tid & 31;
    const int qw = w & 3, kw = w >> 2;
    const int b = blockIdx.y, m0 = blockIdx.x << 7;
    const u32 sb  = smem_u32(smem);
    const u32 sQh = sb, sQl = sb + 16384;
    const u32 sK0 = sb + 32768;
    const u32 sV0 = sb + 98304;

    for (int u = tid; u < 1024; u += 256) {
        int row = u >> 3, ch = u & 7;
        size_t gq = ((size_t)(b * 4096 + m0 + row)) * 64 + ch * 8;
        size_t gk = ((size_t)(b * 4096 + row)) * 64 + ch * 8;
        u32 d = SWZ(row, ch);
        cpa16(sQh + d, g_Qhi + gq);
        cpa16(sQl + d, g_Qlo + gq);
        cpa16(sK0 + d, g_Khi + gk);
        cpa16(sK0 + 16384 + d, g_Klo + gk);
        cpa16(sV0 + d, g_Vh + gk);
    }
    cpa_commit(); cpa_wait0(); __syncthreads();

    const int R = qw << 5;
    u32 qh[8][4], ql[8][4];
    #pragma unroll
    for (int m = 0; m < 2; m++) {
        int arow = R + m * 16 + (l & 15);
        #pragma unroll
        for (int kk = 0; kk < 4; kk++) {
            u32 a = SWZ(arow, kk * 2 + (l >> 4));
            ldsm4(qh[m * 4 + kk], sQh + a);
            ldsm4(ql[m * 4 + kk], sQl + a);
        }
    }

    float esum[2][2] = {{0.f, 0.f}, {0.f, 0.f}};
    float mx[2][2] = {{-1e30f, -1e30f}, {-1e30f, -1e30f}};
    float eacc[2][8][4];
    #pragma unroll
    for (int m = 0; m < 2; m++)
        #pragma unroll
        for (int j = 0; j < 8; j++)
            #pragma unroll
            for (int q = 0; q < 4; q++) eacc[m][j][q] = 0.f;

    const int krow  = (kw << 6) + (l & 7) + ((l & 16) ? 8 : 0);
    const int kcsel = (l >> 3) & 1;
    const int vrow  = (kw << 6) + (l & 7) + ((l & 8) ? 8 : 0);
    const int vcsel = (l >> 4) & 1;

    for (int kt = 0; kt < 32; kt++) {
        const u32 kb = sK0 + (u32)(kt & 1) * 32768;
        const u32 vb = sV0 + (u32)(kt & 1) * 16384;

        if (kt + 1 < 32) {
            int n1 = (kt + 1) << 7;
            u32 kd = sK0 + (u32)((kt + 1) & 1) * 32768;
            u32 vd = sV0 + (u32)((kt + 1) & 1) * 16384;
            for (int u = tid; u < 1024; u += 256) {
                int row = u >> 3, ch = u & 7;
                size_t g = ((size_t)(b * 4096 + n1 + row)) * 64 + ch * 8;
                u32 d = SWZ(row, ch);
                cpa16(kd + d, g_Khi + g);
                cpa16(kd + 16384 + d, g_Klo + g);
                cpa16(vd + d, g_Vh + g);
            }
            cpa_commit();
        }

        #pragma unroll
        for (int sbk = 0; sbk < 2; sbk++) {
            float s[2][4][4];
            #pragma unroll
            for (int m = 0; m < 2; m++)
                #pragma unroll
                for (int nt = 0; nt < 4; nt++)
                    #pragma unroll
                    for (int q = 0; q < 4; q++) s[m][nt][q] = 0.f;

            #pragma unroll
            for (int nt2 = 0; nt2 < 2; nt2++) {
                #pragma unroll
                for (int kk = 0; kk < 4; kk++) {
                    u32 kh[4], klo[4];
                    int rr = sbk * 32 + nt2 * 16 + krow;
                    int ch = kk * 2 + kcsel;
                    ldsm4(kh,  kb + SWZ(rr, ch));
                    ldsm4(klo, kb + 16384 + SWZ(rr, ch));
                    #pragma unroll
                    for (int m = 0; m < 2; m++) {
                        mma_bf16(s[m][nt2 * 2 + 0], qh[m * 4 + kk], kh[0], kh[1]);
                        mma_bf16(s[m][nt2 * 2 + 0], qh[m * 4 + kk], klo[0], klo[1]);
                        mma_bf16(s[m][nt2 * 2 + 0], ql[m * 4 + kk], kh[0], kh[1]);
                        mma_bf16(s[m][nt2 * 2 + 1], qh[m * 4 + kk], kh[2], kh[3]);
                        mma_bf16(s[m][nt2 * 2 + 1], qh[m * 4 + kk], klo[2], klo[3]);
                        mma_bf16(s[m][nt2 * 2 + 1], ql[m * 4 + kk], kh[2], kh[3]);
                    }
                }
            }

            u32 ph[2][2][4];
            #pragma unroll
            for (int m = 0; m < 2; m++) {
                float t0 = s[m][0][0], t1 = s[m][0][2];
                #pragma unroll
                for (int nt = 0; nt < 4; nt++) {
                    t0 = fmaxf(t0, fmaxf(s[m][nt][0], s[m][nt][1]));
                    t1 = fmaxf(t1, fmaxf(s[m][nt][2], s[m][nt][3]));
                }
                t0 = fmaxf(t0, __shfl_xor_sync(0xffffffffu, t0, 1));
                t0 = fmaxf(t0, __shfl_xor_sync(0xffffffffu, t0, 2));
                t1 = fmaxf(t1, __shfl_xor_sync(0xffffffffu, t1, 1));
                t1 = fmaxf(t1, __shfl_xor_sync(0xffffffffu, t1, 2));
                float mn0 = fmaxf(mx[m][0], t0), mn1 = fmaxf(mx[m][1], t1);
                float a0 = __expf(mx[m][0] - mn0), a1 = __expf(mx[m][1] - mn1);
                mx[m][0] = mn0; mx[m][1] = mn1;
                esum[m][0] *= a0; esum[m][1] *= a1;
                #pragma unroll
                for (int j = 0; j < 8; j++) {
                    eacc[m][j][0] *= a0; eacc[m][j][1] *= a0;
                    eacc[m][j][2] *= a1; eacc[m][j][3] *= a1;
                }
                #pragma unroll
                for (int nt = 0; nt < 4; nt++) {
                    float e0 = __expf(s[m][nt][0] - mn0);
                    float e1 = __expf(s[m][nt][1] - mn0);
                    float e2 = __expf(s[m][nt][2] - mn1);
                    float e3 = __expf(s[m][nt][3] - mn1);
                    esum[m][0] += e0 + e1; esum[m][1] += e2 + e3;
                    ph[m][nt >> 1][((nt & 1) << 1) + 0] = pack_f16(e0, e1);
                    ph[m][nt >> 1][((nt & 1) << 1) + 1] = pack_f16(e2, e3);
                }
            }

            #pragma unroll
            for (int t = 0; t < 2; t++) {
                #pragma unroll
                for (int cb = 0; cb < 4; cb++) {
                    u32 vh[4];
                    int rr = sbk * 32 + t * 16 + vrow;
                    int ch = cb * 2 + vcsel;
                    ldsm4t(vh, vb + SWZ(rr, ch));
                    #pragma unroll
                    for (int m = 0; m < 2; m++) {
                        mma_f16(eacc[m][cb * 2 + 0], ph[m][t], vh[0], vh[1]);
                        mma_f16(eacc[m][cb * 2 + 1], ph[m][t], vh[2], vh[3]);
                    }
                }
            }
        }

        cpa_wait0();
        __syncthreads();
    }

    #pragma unroll
    for (int m = 0; m < 2; m++)
        #pragma unroll
        for (int hh = 0; hh < 2; hh++) {
            #pragma unroll
            for (int off = 1; off < 4; off <<= 1)
                esum[m][hh] += __shfl_xor_sync(0xffffffffu, esum[m][hh], off);
        }

    const int gr = l >> 2, c0 = 2 * (l & 3);
    float* sPart = (float*)smem;
    float* sSum  = (float*)(smem + 131072);
    float* sMax  = (float*)(smem + 131584);
    if (kw == 1) {
        #pragma unroll
        for (int m = 0; m < 2; m++) {
            int r0 = R + m * 16 + gr, r1 = r0 + 8;
            #pragma unroll
            for (int j = 0; j < 8; j++) {
                float* p  = &sPart[r0 * 66 + j * 8 + c0];
                float* p2 = &sPart[r1 * 66 + j * 8 + c0];
                p[0]  = eacc[m][j][0]; p[1]  = eacc[m][j][1];
                p2[0] = eacc[m][j][2]; p2[1] = eacc[m][j][3];
            }
            if ((l & 3) == 0) {
                sSum[r0] = esum[m][0]; sSum[r1] = esum[m][1];
                sMax[r0] = mx[m][0];   sMax[r1] = mx[m][1];
            }
        }
    }
    __syncthreads();
    float* sE = (float*)(smem + 65536);
    if (kw == 0) {
        #pragma unroll
        for (int m = 0; m < 2; m++) {
            int r0 = R + m * 16 + gr, r1 = r0 + 8;
            float mb0 = sMax[r0], mb1 = sMax[r1];
            float M0 = fmaxf(mx[m][0], mb0), M1 = fmaxf(mx[m][1], mb1);
            float fa0 = __expf(mx[m][0] - M0), fb0 = __expf(mb0 - M0);
            float fa1 = __expf(mx[m][1] - M1), fb1 = __expf(mb1 - M1);
            float inv0 = 1.f / (esum[m][0] * fa0 + sSum[r0] * fb0);
            float inv1 = 1.f / (esum[m][1] * fa1 + sSum[r1] * fb1);
            #pragma unroll
            for (int j = 0; j < 8; j++) {
                float* p  = &sPart[r0 * 66 + j * 8 + c0];
                float* p2 = &sPart[r1 * 66 + j * 8 + c0];
                int c = 8 * j + c0;
                sE[c * 132 + r0]       = (eacc[m][j][0] * fa0 + p[0]  * fb0) * inv0;
                sE[(c + 1) * 132 + r0] = (eacc[m][j][1] * fa0 + p[1]  * fb0) * inv0;
                sE[c * 132 + r1]       = (eacc[m][j][2] * fa1 + p2[0] * fb1) * inv1;
                sE[(c + 1) * 132 + r1] = (eacc[m][j][3] * fa1 + p2[1] * fb1) * inv1;
            }
        }
    }
    __syncthreads();
    for (int u = tid; u < 2048; u += 256) {
        int c = u >> 5, q = u & 31;
        float4 v = *(float4*)&sE[c * 132 + q * 4];
        *(float4*)&g_E[(((b << 6) + c) << 12) + m0 + q * 4] = v;
    }
}

// ============ Kernel 3: conv3x3 + BN + ReLU + residual (R13, unchanged) ============
__global__ void __launch_bounds__(128) conv_kernel(
    const float* __restrict__ Hp,
    const float* __restrict__ cw, const float* __restrict__ cb,
    const float* __restrict__ gamma, const float* __restrict__ beta,
    const float* __restrict__ mean, const float* __restrict__ var,
    float* __restrict__ out)
{
    extern __shared__ float sW[];
    const int tid = threadIdx.x, b = blockIdx.y, y0 = blockIdx.x << 1;
    const int oh = blockIdx.z << 5;
    for (int i = tid; i < 64 * 9 * 32; i += 128) {
        int ocl = i / 576, rem = i - ocl * 576;
        sW[rem * 32 + ocl] = cw[(oh + ocl) * 576 + rem];
    }
    __syncthreads();
    const int y = y0 + (tid >> 6), x = tid & 63;
    u64 acc2[16];
    #pragma unroll
    for (int i = 0; i < 16; i++) acc2[i] = 0ULL;
    for (int ic = 0; ic < 64; ic++) {
        const float* src = &g_E[(((b << 6) + ic) << 12)];
        float in9[9];
        #pragma unroll
        for (int dy = 0; dy < 3; dy++) {
            int yy = y + dy - 1; bool yok = (yy >= 0) && (yy < 64);
            #pragma unroll
            for (int dx = 0; dx < 3; dx++) {
                int xx = x + dx - 1;
                in9[dy * 3 + dx] = (yok && xx >= 0 && xx < 64) ? src[(yy << 6) + xx] : 0.f;
            }
        }
        #pragma unroll
        for (int kk = 0; kk < 9; kk++) {
            u64 iv = pk2(in9[kk], in9[kk]);
            const u64* wr = (const u64*)&sW[(ic * 9 + kk) << 5];
            #pragma unroll
            for (int q = 0; q < 16; q++) fma2(acc2[q], iv, wr[q]);
        }
    }
    const int pix = (y << 6) + x;
    #pragma unroll
    for (int q = 0; q < 16; q++) {
        float2 a = upk2(acc2[q]);
        #pragma unroll
        for (int h = 0; h < 2; h++) {
            int oc = oh + 2 * q + h;
            float v = (h ? a.y : a.x) + cb[oc];
            v = (v - mean[oc]) * (gamma[oc] * rsqrtf(var[oc] + 1e-5f)) + beta[oc];
            v = fmaxf(v, 0.f);
            int idx = (((b << 6) + oc) << 12) + pix;
            out[idx] = Hp[idx] + v;
        }
    }
}

extern "C" void kernel_launch(void* const* d_in, const int* in_sizes, int n_in,
                              void* d_out, int out_size)
{
    const float* Hp = (const float*)d_in[0];
    const float* Lp = (const float*)d_in[1];
    const float* tw = (const float*)d_in[2];  const float* tb = (const float*)d_in[3];
    const float* pw = (const float*)d_in[4];  const float* pb = (const float*)d_in[5];
    const float* gw = (const float*)d_in[6];  const float* gb = (const float*)d_in[7];
    const float* cw = (const float*)d_in[8];  const float* cb = (const float*)d_in[9];
    const float* gamma = (const float*)d_in[10]; const float* beta = (const float*)d_in[11];
    const float* mean = (const float*)d_in[12];  const float* var = (const float*)d_in[13];
    float* out = (float*)d_out;

    const int smem_conv = 64 * 9 * 32 * 4;
    cudaFuncSetAttribute(proj_kernel, cudaFuncAttributeMaxDynamicSharedMemorySize, PJ_SMEM);
    cudaFuncSetAttribute(attn_kernel, cudaFuncAttributeMaxDynamicSharedMemorySize, ATTN_SMEM);
    cudaFuncSetAttribute(conv_kernel, cudaFuncAttributeMaxDynamicSharedMemorySize, smem_conv);

    proj_kernel<<<dim3(64, 3, 4), 256, PJ_SMEM>>>(Hp, Lp, tw, tb, pw, pb, gw, gb);
    attn_kernel<<<dim3(32, 4), 256, ATTN_SMEM>>>();
    conv_kernel<<<dim3(32, 4, 2), 128, smem_conv>>>(Hp, cw, cb, gamma, beta, mean, var, out);
}

// round 16
// speedup vs baseline: 1.5080x; 1.3302x over previous
#include <cuda_runtime.h>
#include <cuda_bf16.h>
#include <cuda_fp16.h>
typedef unsigned int u32; typedef unsigned long long u64;

#define NELEM (4*4096*64)
__device__ __nv_bfloat16 g_Khi[NELEM], g_Klo[NELEM];   // [b][n][c]
__device__ __nv_bfloat16 g_Qhi[NELEM], g_Qlo[NELEM];   // [b][m][c]
__device__ __half        g_Vh [NELEM];                  // [b][n][c]  fp16
__device__ __nv_bfloat16 g_Ehi[NELEM], g_Elo[NELEM];   // [b][px][c] split bf16
__device__ __nv_bfloat16 g_Whi[9*64*64], g_Wlo[9*64*64]; // [s][oc][ic]

#define SWZ(row, chunk) (((u32)(row) << 7) + ((u32)(((chunk) ^ ((row) & 7))) << 4))

__device__ __forceinline__ u32 smem_u32(const void* p) {
    u32 a; asm("{ .reg .u64 t; cvta.to.shared.u64 t, %1; cvt.u32.u64 %0, t; }" : "=r"(a) : "l"(p)); return a;
}
__device__ __forceinline__ void cpa16(u32 dst, const void* src) {
    asm volatile("cp.async.cg.shared.global [%0], [%1], 16;" :: "r"(dst), "l"(src));
}
__device__ __forceinline__ void cpa_commit() { asm volatile("cp.async.commit_group;"); }
__device__ __forceinline__ void cpa_wait0()  { asm volatile("cp.async.wait_group 0;"); }
__device__ __forceinline__ void ldsm4(u32* r, u32 a) {
    asm volatile("ldmatrix.sync.aligned.m8n8.x4.shared.b16 {%0,%1,%2,%3},[%4];"
        : "=r"(r[0]), "=r"(r[1]), "=r"(r[2]), "=r"(r[3]) : "r"(a));
}
__device__ __forceinline__ void ldsm4t(u32* r, u32 a) {
    asm volatile("ldmatrix.sync.aligned.m8n8.x4.trans.shared.b16 {%0,%1,%2,%3},[%4];"
        : "=r"(r[0]), "=r"(r[1]), "=r"(r[2]), "=r"(r[3]) : "r"(a));
}
__device__ __forceinline__ void mma_bf16(float* d, const u32* a, u32 b0, u32 b1) {
    asm volatile("mma.sync.aligned.m16n8k16.row.col.f32.bf16.bf16.f32 "
        "{%0,%1,%2,%3},{%4,%5,%6,%7},{%8,%9},{%0,%1,%2,%3};"
        : "+f"(d[0]), "+f"(d[1]), "+f"(d[2]), "+f"(d[3])
        : "r"(a[0]), "r"(a[1]), "r"(a[2]), "r"(a[3]), "r"(b0), "r"(b1));
}
__device__ __forceinline__ void mma_f16(float* d, const u32* a, u32 b0, u32 b1) {
    asm volatile("mma.sync.aligned.m16n8k16.row.col.f32.f16.f16.f32 "
        "{%0,%1,%2,%3},{%4,%5,%6,%7},{%8,%9},{%0,%1,%2,%3};"
        : "+f"(d[0]), "+f"(d[1]), "+f"(d[2]), "+f"(d[3])
        : "r"(a[0]), "r"(a[1]), "r"(a[2]), "r"(a[3]), "r"(b0), "r"(b1));
}
__device__ __forceinline__ u32 pack_f16(float lo, float hi) {
    __half2 h = __floats2half2_rn(lo, hi);
    return *(u32*)&h;
}
__device__ __forceinline__ u32 pack_bf16(float lo, float hi) {
    u32 r; asm("cvt.rn.bf16x2.f32 %0, %1, %2;" : "=r"(r) : "f"(hi), "f"(lo)); return r;
}

// ========== Kernel 0: split conv weights -> [s][oc][ic] bf16 hi/lo ================
__global__ void __launch_bounds__(256) wtrans_kernel(const float* __restrict__ cw)
{
    int i = blockIdx.x * 256 + threadIdx.x;
    if (i >= 9 * 64 * 64) return;
    int s = i >> 12, rem = i & 4095, oc = rem >> 6, ic = rem & 63;
    float v = cw[(oc * 64 + ic) * 9 + s];
    __nv_bfloat16 h = __float2bfloat16_rn(v);
    g_Whi[i] = h;
    g_Wlo[i] = __float2bfloat16_rn(v - __bfloat162float(h));
}

// ========== Kernel 1: HMMA projections (R14, unchanged) ===========================
#define PJ_SMEM 65536

__global__ void __launch_bounds__(256, 3) proj_kernel(
    const float* __restrict__ Hp, const float* __restrict__ Lp,
    const float* __restrict__ tw, const float* __restrict__ tb,
    const float* __restrict__ pw, const float* __restrict__ pb,
    const float* __restrict__ gw, const float* __restrict__ gb)
{
    extern __shared__ char smc[];
    const u32 sb = smem_u32(smc);
    const int proj = blockIdx.y, b = blockIdx.z, p0 = blockIdx.x << 6, tid = threadIdx.x;
    const int w = tid >> 5, l = tid & 31;
    const float* W; const float* bias; int IC;
    if (proj == 0)      { W = tw; bias = tb; IC = 128; }
    else if (proj == 1) { W = pw; bias = pb; IC = 128; }
    else                { W = gw; bias = gb; IC = 64;  }

    for (int u = tid; u < IC * 32; u += 256) {
        int c = u >> 5, pp = (u & 31) << 1;
        const float* src = (proj == 2) ? Lp : ((c < 64) ? Hp : Lp);
        const float* s2 = &src[(((b << 6) + (c & 63)) << 12) + p0 + pp];
        float v0 = s2[0], v1 = s2[1];
        u32 hh = pack_bf16(v0, v1);
        float h0 = __uint_as_float(hh << 16), h1 = __uint_as_float(hh & 0xffff0000u);
        u32 ll = pack_bf16(v0 - h0, v1 - h1);
        u32 off = SWZ(c, pp >> 3) + ((pp & 7) << 1);
        *(u32*)(smc + off) = hh;
        *(u32*)(smc + 16384 + off) = ll;
    }
    for (int u = tid; u < 64 * (IC >> 1); u += 256) {
        int oc = u / (IC >> 1), cp = (u % (IC >> 1)) << 1;
        float w0 = W[oc * IC + cp], w1 = W[oc * IC + cp + 1];
        u32 hh = pack_bf16(w0, w1);
        float h0 = __uint_as_float(hh << 16), h1 = __uint_as_float(hh & 0xffff0000u);
        u32 ll = pack_bf16(w0 - h0, w1 - h1);
        int half = cp >> 6, cl = cp & 63;
        u32 off = ((u32)half << 13) + SWZ(oc, cl >> 3) + ((cl & 7) << 1);
        *(u32*)(smc + 32768 + off) = hh;
        *(u32*)(smc + 49152 + off) = ll;
    }
    __syncthreads();

    const int mt = w & 3, pxh = w >> 2;
    const int arow = mt * 16 + (l & 15);
    const int acs = l >> 4;
    const int brr = (l & 7) + ((l & 8) ? 8 : 0);
    const int bcs = (l >> 4) & 1;

    float acc[4][4];
    #pragma unroll
    for (int j = 0; j < 4; j++)
        #pragma unroll
        for (int q = 0; q < 4; q++) acc[j][q] = 0.f;

    const int K16 = IC >> 4;
    #pragma unroll 4
    for (int kk = 0; kk < K16; kk++) {
        u32 wh[4], wl[4];
        u32 aoff = ((u32)(kk >> 2) << 13) + SWZ(arow, ((kk & 3) << 1) + acs);
        ldsm4(wh, sb + 32768 + aoff);
        ldsm4(wl, sb + 49152 + aoff);
        int rr = (kk << 4) + brr;
        #pragma unroll
        for (int nb = 0; nb < 2; nb++) {
            u32 xh[4], xl[4];
            u32 boff = SWZ(rr, (pxh << 2) + (nb << 1) + bcs);
            ldsm4t(xh, sb + boff);
            ldsm4t(xl, sb + 16384 + boff);
            mma_bf16(acc[nb * 2 + 0], wh, xh[0], xh[1]);
            mma_bf16(acc[nb * 2 + 0], wh, xl[0], xl[1]);
            mma_bf16(acc[nb * 2 + 0], wl, xh[0], xh[1]);
            mma_bf16(acc[nb * 2 + 1], wh, xh[2], xh[3]);
            mma_bf16(acc[nb * 2 + 1], wh, xl[2], xl[3]);
            mma_bf16(acc[nb * 2 + 1], wl, xh[2], xh[3]);
        }
    }
    __syncthreads();

    unsigned short* tHi = (unsigned short*)smc;
    unsigned short* tLo = (unsigned short*)(smc + 9216);
    const int r0 = mt * 16 + (l >> 2), r1 = r0 + 8;
    const float b0v = bias[r0], b1v = bias[r1];
    #pragma unroll
    for (int j = 0; j < 4; j++) {
        int px = pxh * 32 + j * 8 + ((l & 3) << 1);
        float v00 = acc[j][0] + b0v, v01 = acc[j][1] + b0v;
        float v10 = acc[j][2] + b1v, v11 = acc[j][3] + b1v;
        if (proj == 2) {
            tHi[px * 72 + r0]       = __half_as_ushort(__float2half_rn(v00));
            tHi[(px + 1) * 72 + r0] = __half_as_ushort(__float2half_rn(v01));
            tHi[px * 72 + r1]       = __half_as_ushort(__float2half_rn(v10));
            tHi[(px + 1) * 72 + r1] = __half_as_ushort(__float2half_rn(v11));
        } else {
            __nv_bfloat16 h00 = __float2bfloat16_rn(v00), h01 = __float2bfloat16_rn(v01);
            __nv_bfloat16 h10 = __float2bfloat16_rn(v10), h11 = __float2bfloat16_rn(v11);
            tHi[px * 72 + r0]       = *(unsigned short*)&h00;
            tHi[(px + 1) * 72 + r0] = *(unsigned short*)&h01;
            tHi[px * 72 + r1]       = *(unsigned short*)&h10;
            tHi[(px + 1) * 72 + r1] = *(unsigned short*)&h11;
            __nv_bfloat16 l00 = __float2bfloat16_rn(v00 - __bfloat162float(h00));
            __nv_bfloat16 l01 = __float2bfloat16_rn(v01 - __bfloat162float(h01));
            __nv_bfloat16 l10 = __float2bfloat16_rn(v10 - __bfloat162float(h10));
            __nv_bfloat16 l11 = __float2bfloat16_rn(v11 - __bfloat162float(h11));
            tLo[px * 72 + r0]       = *(unsigned short*)&l00;
            tLo[(px + 1) * 72 + r0] = *(unsigned short*)&l01;
            tLo[px * 72 + r1]       = *(unsigned short*)&l10;
            tLo[(px + 1) * 72 + r1] = *(unsigned short*)&l11;
        }
    }
    __syncthreads();
    if (proj == 2) {
        uint4* dh = (uint4*)(g_Vh + ((size_t)b * 4096 + p0) * 64);
        for (int u = tid; u < 512; u += 256) {
            int row = u >> 3, cc = u & 7;
            dh[u] = *(const uint4*)&tHi[row * 72 + cc * 8];
        }
    } else {
        __nv_bfloat16* dHi = (proj == 0) ? g_Khi : g_Qhi;
        __nv_bfloat16* dLo = (proj == 0) ? g_Klo : g_Qlo;
        uint4* dh = (uint4*)(dHi + ((size_t)b * 4096 + p0) * 64);
        uint4* dl = (uint4*)(dLo + ((size_t)b * 4096 + p0) * 64);
        for (int u = tid; u < 512; u += 256) {
            int row = u >> 3, cc = u & 7;
            dh[u] = *(const uint4*)&tHi[row * 72 + cc * 8];
            dl[u] = *(const uint4*)&tLo[row * 72 + cc * 8];
        }
    }
}

// ================= Kernel 2: HMMA flash attention (split-bf16 E epilogue) =========
#define ATTN_SMEM 132096

__global__ void __launch_bounds__(256, 1) attn_kernel()
{
    extern __shared__ char smem[];
    const int tid = threadIdx.x, w = tid >> 5, l = tid & 31;
    const int qw = w & 3, kw = w >> 2;
    const int b = blockIdx.y, m0 = blockIdx.x << 7;
    const u32 sb  = smem_u32(smem);
    const u32 sQh = sb, sQl = sb + 16384;
    const u32 sK0 = sb + 32768;
    const u32 sV0 = sb + 98304;

    for (int u = tid; u < 1024; u += 256) {
        int row = u >> 3, ch = u & 7;
        size_t gq = ((size_t)(b * 4096 + m0 + row)) * 64 + ch * 8;
        size_t gk = ((size_t)(b * 4096 + row)) * 64 + ch * 8;
        u32 d = SWZ(row, ch);
        cpa16(sQh + d, g_Qhi + gq);
        cpa16(sQl + d, g_Qlo + gq);
        cpa16(sK0 + d, g_Khi + gk);
        cpa16(sK0 + 16384 + d, g_Klo + gk);
        cpa16(sV0 + d, g_Vh + gk);
    }
    cpa_commit(); cpa_wait0(); __syncthreads();

    const int R = qw << 5;
    u32 qh[8][4], ql[8][4];
    #pragma unroll
    for (int m = 0; m < 2; m++) {
        int arow = R + m * 16 + (l & 15);
        #pragma unroll
        for (int kk = 0; kk < 4; kk++) {
            u32 a = SWZ(arow, kk * 2 + (l >> 4));
            ldsm4(qh[m * 4 + kk], sQh + a);
            ldsm4(ql[m * 4 + kk], sQl + a);
        }
    }

    float esum[2][2] = {{0.f, 0.f}, {0.f, 0.f}};
    float mx[2][2] = {{-1e30f, -1e30f}, {-1e30f, -1e30f}};
    float eacc[2][8][4];
    #pragma unroll
    for (int m = 0; m < 2; m++)
        #pragma unroll
        for (int j = 0; j < 8; j++)
            #pragma unroll
            for (int q = 0; q < 4; q++) eacc[m][j][q] = 0.f;

    const int krow  = (kw << 6) + (l & 7) + ((l & 16) ? 8 : 0);
    const int kcsel = (l >> 3) & 1;
    const int vrow  = (kw << 6) + (l & 7) + ((l & 8) ? 8 : 0);
    const int vcsel = (l >> 4) & 1;

    for (int kt = 0; kt < 32; kt++) {
        const u32 kb = sK0 + (u32)(kt & 1) * 32768;
        const u32 vb = sV0 + (u32)(kt & 1) * 16384;

        if (kt + 1 < 32) {
            int n1 = (kt + 1) << 7;
            u32 kd = sK0 + (u32)((kt + 1) & 1) * 32768;
            u32 vd = sV0 + (u32)((kt + 1) & 1) * 16384;
            for (int u = tid; u < 1024; u += 256) {
                int row = u >> 3, ch = u & 7;
                size_t g = ((size_t)(b * 4096 + n1 + row)) * 64 + ch * 8;
                u32 d = SWZ(row, ch);
                cpa16(kd + d, g_Khi + g);
                cpa16(kd + 16384 + d, g_Klo + g);
                cpa16(vd + d, g_Vh + g);
            }
            cpa_commit();
        }

        #pragma unroll
        for (int sbk = 0; sbk < 2; sbk++) {
            float s[2][4][4];
            #pragma unroll
            for (int m = 0; m < 2; m++)
                #pragma unroll
                for (int nt = 0; nt < 4; nt++)
                    #pragma unroll
                    for (int q = 0; q < 4; q++) s[m][nt][q] = 0.f;

            #pragma unroll
            for (int nt2 = 0; nt2 < 2; nt2++) {
                #pragma unroll
                for (int kk = 0; kk < 4; kk++) {
                    u32 kh[4], klo[4];
                    int rr = sbk * 32 + nt2 * 16 + krow;
                    int ch = kk * 2 + kcsel;
                    ldsm4(kh,  kb + SWZ(rr, ch));
                    ldsm4(klo, kb + 16384 + SWZ(rr, ch));
                    #pragma unroll
                    for (int m = 0; m < 2; m++) {
                        mma_bf16(s[m][nt2 * 2 + 0], qh[m * 4 + kk], kh[0], kh[1]);
                        mma_bf16(s[m][nt2 * 2 + 0], qh[m * 4 + kk], klo[0], klo[1]);
                        mma_bf16(s[m][nt2 * 2 + 0], ql[m * 4 + kk], kh[0], kh[1]);
                        mma_bf16(s[m][nt2 * 2 + 1], qh[m * 4 + kk], kh[2], kh[3]);
                        mma_bf16(s[m][nt2 * 2 + 1], qh[m * 4 + kk], klo[2], klo[3]);
                        mma_bf16(s[m][nt2 * 2 + 1], ql[m * 4 + kk], kh[2], kh[3]);
                    }
                }
            }

            u32 ph[2][2][4];
            #pragma unroll
            for (int m = 0; m < 2; m++) {
                float t0 = s[m][0][0], t1 = s[m][0][2];
                #pragma unroll
                for (int nt = 0; nt < 4; nt++) {
                    t0 = fmaxf(t0, fmaxf(s[m][nt][0], s[m][nt][1]));
                    t1 = fmaxf(t1, fmaxf(s[m][nt][2], s[m][nt][3]));
                }
                t0 = fmaxf(t0, __shfl_xor_sync(0xffffffffu, t0, 1));
                t0 = fmaxf(t0, __shfl_xor_sync(0xffffffffu, t0, 2));
                t1 = fmaxf(t1, __shfl_xor_sync(0xffffffffu, t1, 1));
                t1 = fmaxf(t1, __shfl_xor_sync(0xffffffffu, t1, 2));
                float mn0 = fmaxf(mx[m][0], t0), mn1 = fmaxf(mx[m][1], t1);
                float a0 = __expf(mx[m][0] - mn0), a1 = __expf(mx[m][1] - mn1);
                mx[m][0] = mn0; mx[m][1] = mn1;
                esum[m][0] *= a0; esum[m][1] *= a1;
                #pragma unroll
                for (int j = 0; j < 8; j++) {
                    eacc[m][j][0] *= a0; eacc[m][j][1] *= a0;
                    eacc[m][j][2] *= a1; eacc[m][j][3] *= a1;
                }
                #pragma unroll
                for (int nt = 0; nt < 4; nt++) {
                    float e0 = __expf(s[m][nt][0] - mn0);
                    float e1 = __expf(s[m][nt][1] - mn0);
                    float e2 = __expf(s[m][nt][2] - mn1);
                    float e3 = __expf(s[m][nt][3] - mn1);
                    esum[m][0] += e0 + e1; esum[m][1] += e2 + e3;
                    ph[m][nt >> 1][((nt & 1) << 1) + 0] = pack_f16(e0, e1);
                    ph[m][nt >> 1][((nt & 1) << 1) + 1] = pack_f16(e2, e3);
                }
            }

            #pragma unroll
            for (int t = 0; t < 2; t++) {
                #pragma unroll
                for (int cb = 0; cb < 4; cb++) {
                    u32 vh[4];
                    int rr = sbk * 32 + t * 16 + vrow;
                    int ch = cb * 2 + vcsel;
                    ldsm4t(vh, vb + SWZ(rr, ch));
                    #pragma unroll
                    for (int m = 0; m < 2; m++) {
                        mma_f16(eacc[m][cb * 2 + 0], ph[m][t], vh[0], vh[1]);
                        mma_f16(eacc[m][cb * 2 + 1], ph[m][t], vh[2], vh[3]);
                    }
                }
            }
        }

        cpa_wait0();
        __syncthreads();
    }

    #pragma unroll
    for (int m = 0; m < 2; m++)
        #pragma unroll
        for (int hh = 0; hh < 2; hh++) {
            #pragma unroll
            for (int off = 1; off < 4; off <<= 1)
                esum[m][hh] += __shfl_xor_sync(0xffffffffu, esum[m][hh], off);
        }

    const int gr = l >> 2, c0 = 2 * (l & 3);
    float* sPart = (float*)smem;
    float* sSum  = (float*)(smem + 131072);
    float* sMax  = (float*)(smem + 131584);
    if (kw == 1) {
        #pragma unroll
        for (int m = 0; m < 2; m++) {
            int r0 = R + m * 16 + gr, r1 = r0 + 8;
            #pragma unroll
            for (int j = 0; j < 8; j++) {
                float* p  = &sPart[r0 * 66 + j * 8 + c0];
                float* p2 = &sPart[r1 * 66 + j * 8 + c0];
                p[0]  = eacc[m][j][0]; p[1]  = eacc[m][j][1];
                p2[0] = eacc[m][j][2]; p2[1] = eacc[m][j][3];
            }
            if ((l & 3) == 0) {
                sSum[r0] = esum[m][0]; sSum[r1] = esum[m][1];
                sMax[r0] = mx[m][0];   sMax[r1] = mx[m][1];
            }
        }
    }
    __syncthreads();
    if (kw == 0) {
        #pragma unroll
        for (int m = 0; m < 2; m++) {
            int r0 = R + m * 16 + gr, r1 = r0 + 8;
            float mb0 = sMax[r0], mb1 = sMax[r1];
            float M0 = fmaxf(mx[m][0], mb0), M1 = fmaxf(mx[m][1], mb1);
            float fa0 = __expf(mx[m][0] - M0), fb0 = __expf(mb0 - M0);
            float fa1 = __expf(mx[m][1] - M1), fb1 = __expf(mb1 - M1);
            float inv0 = 1.f / (esum[m][0] * fa0 + sSum[r0] * fb0);
            float inv1 = 1.f / (esum[m][1] * fa1 + sSum[r1] * fb1);
            u32* eh0 = (u32*)(g_Ehi + ((size_t)(b * 4096 + m0 + r0)) * 64);
            u32* el0 = (u32*)(g_Elo + ((size_t)(b * 4096 + m0 + r0)) * 64);
            u32* eh1 = (u32*)(g_Ehi + ((size_t)(b * 4096 + m0 + r1)) * 64);
            u32* el1 = (u32*)(g_Elo + ((size_t)(b * 4096 + m0 + r1)) * 64);
            #pragma unroll
            for (int j = 0; j < 8; j++) {
                int c = 8 * j + c0;
                float v0 = (eacc[m][j][0] * fa0 + sPart[r0 * 66 + c] * fb0) * inv0;
                float v1 = (eacc[m][j][1] * fa0 + sPart[r0 * 66 + c + 1] * fb0) * inv0;
                float v2 = (eacc[m][j][2] * fa1 + sPart[r1 * 66 + c] * fb1) * inv1;
                float v3 = (eacc[m][j][3] * fa1 + sPart[r1 * 66 + c + 1] * fb1) * inv1;
                u32 h01 = pack_bf16(v0, v1);
                u32 h23 = pack_bf16(v2, v3);
                eh0[c >> 1] = h01;
                eh1[c >> 1] = h23;
                float r0a = v0 - __uint_as_float(h01 << 16);
                float r0b = v1 - __uint_as_float(h01 & 0xffff0000u);
                float r1a = v2 - __uint_as_float(h23 << 16);
                float r1b = v3 - __uint_as_float(h23 & 0xffff0000u);
                el0[c >> 1] = pack_bf16(r0a, r0b);
                el1[c >> 1] = pack_bf16(r1a, r1b);
            }
        }
    }
}

// ====== Kernel 3: conv3x3 via HMMA implicit GEMM + BN + ReLU + residual ===========
// smem: Ehi [264 brow][144B] 0..38016 | Elo at 38016..76032  (144B rows, 16B-aligned)
#define CV_LO 38016
#define CV_SMEM 76032

__global__ void __launch_bounds__(256) conv_kernel(
    const float* __restrict__ Hp,
    const float* __restrict__ cb,
    const float* __restrict__ gamma, const float* __restrict__ beta,
    const float* __restrict__ mean, const float* __restrict__ var,
    float* __restrict__ out)
{
    extern __shared__ char smc[];
    const int tid = threadIdx.x, w = tid >> 5, l = tid & 31;
    const int b = blockIdx.y, y0 = blockIdx.x << 1;

    // stage E rows y0-1..y0+2, x -1..64 (zero-padded), [brow][64 ic], 144B stride
    for (int u = tid; u < 2112; u += 256) {
        int brow = u >> 3, ch = u & 7;
        int yp = brow / 66, xi = brow - yp * 66;
        int yg = y0 - 1 + yp, xg = xi - 1;
        uint4 vh = make_uint4(0, 0, 0, 0), vl = vh;
        if (yg >= 0 && yg < 64 && xg >= 0 && xg < 64) {
            size_t g = ((size_t)(b * 4096 + yg * 64 + xg)) * 64 + ch * 8;
            vh = *(const uint4*)(g_Ehi + g);
            vl = *(const uint4*)(g_Elo + g);
        }
        *(uint4*)(smc + brow * 144 + ch * 16) = vh;
        *(uint4*)(smc + CV_LO + brow * 144 + ch * 16) = vl;
    }
    __syncthreads();

    const int mt = w & 3, nh = w >> 2;   // 4 oc tiles x 2 row-halves
    const int lr = l >> 2, lc = l & 3;

    float acc[8][4];
    #pragma unroll
    for (int n8 = 0; n8 < 8; n8++)
        #pragma unroll
        for (int q = 0; q < 4; q++) acc[n8][q] = 0.f;

    #pragma unroll 1
    for (int s = 0; s < 9; s++) {
        const int dy = s / 3, dx = s - dy * 3;
        const int browb = (nh + dy) * 66 + dx + lr;
        #pragma unroll
        for (int kc = 0; kc < 4; kc++) {
            const __nv_bfloat16* wb  = g_Whi + (size_t)s * 4096 + (mt * 16 + lr) * 64 + kc * 16 + lc * 2;
            const __nv_bfloat16* wlb = g_Wlo + (size_t)s * 4096 + (mt * 16 + lr) * 64 + kc * 16 + lc * 2;
            u32 ah[4], al[4];
            ah[0] = *(const u32*)wb;          ah[1] = *(const u32*)(wb + 512);
            ah[2] = *(const u32*)(wb + 8);    ah[3] = *(const u32*)(wb + 520);
            al[0] = *(const u32*)wlb;         al[1] = *(const u32*)(wlb + 512);
            al[2] = *(const u32*)(wlb + 8);   al[3] = *(const u32*)(wlb + 520);
            const u32 koff = kc * 32 + lc * 4;
            #pragma unroll
            for (int n8 = 0; n8 < 8; n8++) {
                u32 ba = (u32)(browb + n8 * 8) * 144 + koff;
                u32 bh0 = *(const u32*)(smc + ba);
                u32 bh1 = *(const u32*)(smc + ba + 16);
                u32 bl0 = *(const u32*)(smc + CV_LO + ba);
                u32 bl1 = *(const u32*)(smc + CV_LO + ba + 16);
                mma_bf16(acc[n8], ah, bh0, bh1);
                mma_bf16(acc[n8], ah, bl0, bl1);
                mma_bf16(acc[n8], al, bh0, bh1);
            }
        }
    }

    const int oc0 = mt * 16 + lr, oc1 = oc0 + 8;
    const float bia0 = cb[oc0], bia1 = cb[oc1];
    const float sc0 = gamma[oc0] * rsqrtf(var[oc0] + 1e-5f);
    const float sc1 = gamma[oc1] * rsqrtf(var[oc1] + 1e-5f);
    const float me0 = mean[oc0], me1 = mean[oc1];
    const float be0 = beta[oc0], be1 = beta[oc1];
    #pragma unroll
    for (int n8 = 0; n8 < 8; n8++) {
        int px = (y0 + nh) * 64 + n8 * 8 + lc * 2;
        size_t i0 = ((size_t)(b * 64 + oc0)) * 4096 + px;
        size_t i1 = ((size_t)(b * 64 + oc1)) * 4096 + px;
        float v0 = fmaxf((acc[n8][0] + bia0 - me0) * sc0 + be0, 0.f);
        float v1 = fmaxf((acc[n8][1] + bia0 - me0) * sc0 + be0, 0.f);
        float v2 = fmaxf((acc[n8][2] + bia1 - me1) * sc1 + be1, 0.f);
        float v3 = fmaxf((acc[n8][3] + bia1 - me1) * sc1 + be1, 0.f);
        float2 h0 = *(const float2*)&Hp[i0];
        float2 h1 = *(const float2*)&Hp[i1];
        *(float2*)&out[i0] = make_float2(h0.x + v0, h0.y + v1);
        *(float2*)&out[i1] = make_float2(h1.x + v2, h1.y + v3);
    }
}

extern "C" void kernel_launch(void* const* d_in, const int* in_sizes, int n_in,
                              void* d_out, int out_size)
{
    const float* Hp = (const float*)d_in[0];
    const float* Lp = (const float*)d_in[1];
    const float* tw = (const float*)d_in[2];  const float* tb = (const float*)d_in[3];
    const float* pw = (const float*)d_in[4];  const float* pb = (const float*)d_in[5];
    const float* gw = (const float*)d_in[6];  const float* gb = (const float*)d_in[7];
    const float* cw = (const float*)d_in[8];  const float* cb = (const float*)d_in[9];
    const float* gamma = (const float*)d_in[10]; const float* beta = (const float*)d_in[11];
    const float* mean = (const float*)d_in[12];  const float* var = (const float*)d_in[13];
    float* out = (float*)d_out;

    cudaFuncSetAttribute(proj_kernel, cudaFuncAttributeMaxDynamicSharedMemorySize, PJ_SMEM);
    cudaFuncSetAttribute(attn_kernel, cudaFuncAttributeMaxDynamicSharedMemorySize, ATTN_SMEM);
    cudaFuncSetAttribute(conv_kernel, cudaFuncAttributeMaxDynamicSharedMemorySize, CV_SMEM);

    wtrans_kernel<<<144, 256>>>(cw);
    proj_kernel<<<dim3(64, 3, 4), 256, PJ_SMEM>>>(Hp, Lp, tw, tb, pw, pb, gw, gb);
    attn_kernel<<<dim3(32, 4), 256, ATTN_SMEM>>>();
    conv_kernel<<<dim3(32, 4), 256, CV_SMEM>>>(Hp, cb, gamma, beta, mean, var, out);
}